// round 8
// baseline (speedup 1.0000x reference)
#include <cuda_runtime.h>
#include <mma.h>
#include <cstddef>

using namespace nvcuda;

// ---------------------------------------------------------------------------
// S4Layer: B=8, L=2048, D=1024
//   M = C_w @ A_w ; P = M @ Wx ; Q = M @ Wy ; c = M @ rc_b
//   u_t = x[:,t] @ P^T + c   (t = 1..2047)
//   y_0 = x[:,0] ;  y_t = u_t + Q y_{t-1}
// Chunked scan: 64 chunks of S=32 (two passes + carry chain).
// All GEMMs on tensor pipe: mma.sync tf32 with 2-term split (3 MMAs) for
// ~fp32 accuracy. fp32 everywhere in memory.
// ---------------------------------------------------------------------------

#define DM 1024
#define NB 8
#define LSEQ 2048
#define SCH 32
#define NCH 64
#define R1 504   // pass-1 rows = 63 chunks * 8 batch
#define R2 512   // pass-2 rows = 64 chunks * 8 batch
#define NROW_U (NB * (LSEQ - 1))   // 16376

__device__ float g_M [DM * DM];
__device__ float g_P [DM * DM];
__device__ float g_Q [DM * DM];
__device__ float g_Wy[DM * DM];
__device__ float g_T1[DM * DM];
__device__ float g_T2[DM * DM];
__device__ float g_QS[DM * DM];
__device__ float g_cvec[DM];
__device__ float g_W0[R1 * DM];
__device__ float g_W1[R1 * DM];
__device__ float g_Cst[NCH * NB * DM];

#define BUF_M  0
#define BUF_P  1
#define BUF_Q  2
#define BUF_WY 3
#define BUF_T1 4
#define BUF_T2 5
#define BUF_QS 6

__device__ __forceinline__ float* sel_buf(int i)
{
    switch (i) {
        case BUF_M:  return g_M;
        case BUF_P:  return g_P;
        case BUF_Q:  return g_Q;
        case BUF_WY: return g_Wy;
        case BUF_T1: return g_T1;
        case BUF_T2: return g_T2;
        default:     return g_QS;
    }
}

typedef wmma::fragment<wmma::matrix_a, 16, 16, 8, wmma::precision::tf32, wmma::row_major> frag_a_t;
typedef wmma::fragment<wmma::matrix_b, 16, 16, 8, wmma::precision::tf32, wmma::col_major> frag_bc_t;
typedef wmma::fragment<wmma::matrix_b, 16, 16, 8, wmma::precision::tf32, wmma::row_major> frag_br_t;
typedef wmma::fragment<wmma::accumulator, 16, 16, 8, float> frag_c_t;

template <class F>
__device__ __forceinline__ void split_tf32(const F& src, F& hi, F& lo)
{
#pragma unroll
    for (int i = 0; i < src.num_elements; i++) {
        float h = wmma::__float_to_tf32(src.x[i]);
        hi.x[i] = h;
        lo.x[i] = wmma::__float_to_tf32(src.x[i] - h);
    }
}

// --------------------------------------------------------------------------
// Wy[k][d] = rc_w[k, D+d] + rc_w[k, 2D+d]
__global__ void k_prep_wy(const float* __restrict__ rc_w)
{
    int idx = blockIdx.x * blockDim.x + threadIdx.x;   // 1M elements
    int k = idx >> 10, d = idx & 1023;
    g_Wy[idx] = rc_w[k * 3072 + 1024 + d] + rc_w[k * 3072 + 2048 + d];
}

// --------------------------------------------------------------------------
// NN GEMM (tensor): C[1024,1024] = A[1024,1024] @ B[1024, n-slice] (both row-major).
// CTA tile 64x64, 128 threads (4 warps 2x2), warp tile 32x32, k-chunk 32.
__global__ void __launch_bounds__(128)
k_nn(const float* extA, const float* extB, int ia, int ib, int ic, int ldb)
{
    const float* A  = (ia >= 0) ? sel_buf(ia) : extA;
    const float* Bm = (ib >= 0) ? sel_buf(ib) : extB;
    float*       Cm = sel_buf(ic);

    __shared__ __align__(16) float As[64][36];
    __shared__ __align__(16) float Bs[32][68];

    const int tid  = threadIdx.x;
    const int warp = tid >> 5;
    const int wr   = warp >> 1, wc = warp & 1;
    const int row0 = blockIdx.y * 64, col0 = blockIdx.x * 64;

    frag_c_t acc[2][2];
#pragma unroll
    for (int i = 0; i < 2; i++)
#pragma unroll
        for (int j = 0; j < 2; j++) wmma::fill_fragment(acc[i][j], 0.f);

    for (int k0 = 0; k0 < 1024; k0 += 32) {
#pragma unroll
        for (int l = 0; l < 4; l++) {          // A: 512 float4
            int id = tid + l * 128;
            int r = id >> 3, c4 = (id & 7) * 4;
            *(float4*)&As[r][c4] =
                *(const float4*)(A + (size_t)(row0 + r) * 1024 + k0 + c4);
        }
#pragma unroll
        for (int l = 0; l < 4; l++) {          // B: 512 float4
            int id = tid + l * 128;
            int k = id >> 4, n4 = (id & 15) * 4;
            *(float4*)&Bs[k][n4] =
                *(const float4*)(Bm + (size_t)(k0 + k) * ldb + col0 + n4);
        }
        __syncthreads();
#pragma unroll
        for (int kk = 0; kk < 4; kk++) {
            frag_a_t araw, ahi[2], alo[2];
            frag_br_t braw, bhi[2], blo[2];
#pragma unroll
            for (int i = 0; i < 2; i++) {
                wmma::load_matrix_sync(araw, &As[wr * 32 + i * 16][kk * 8], 36);
                split_tf32(araw, ahi[i], alo[i]);
            }
#pragma unroll
            for (int j = 0; j < 2; j++) {
                wmma::load_matrix_sync(braw, &Bs[kk * 8][wc * 32 + j * 16], 68);
                split_tf32(braw, bhi[j], blo[j]);
            }
#pragma unroll
            for (int i = 0; i < 2; i++)
#pragma unroll
                for (int j = 0; j < 2; j++) {
                    wmma::mma_sync(acc[i][j], ahi[i], bhi[j], acc[i][j]);
                    wmma::mma_sync(acc[i][j], alo[i], bhi[j], acc[i][j]);
                    wmma::mma_sync(acc[i][j], ahi[i], blo[j], acc[i][j]);
                }
        }
        __syncthreads();
    }
#pragma unroll
    for (int i = 0; i < 2; i++)
#pragma unroll
        for (int j = 0; j < 2; j++)
            wmma::store_matrix_sync(
                Cm + (size_t)(row0 + wr * 32 + i * 16) * 1024 + col0 + wc * 32 + j * 16,
                acc[i][j], 1024, wmma::mem_row_major);
}

// --------------------------------------------------------------------------
// g_cvec[e] = sum_k g_M[e,k] * rc_b[k]
__global__ void k_matvec_c(const float* __restrict__ rc_b)
{
    int e = blockIdx.x * 8 + (threadIdx.x >> 5);
    int lane = threadIdx.x & 31;
    const float* mr = g_M + (size_t)e * 1024;
    float acc = 0.f;
#pragma unroll 4
    for (int d = lane; d < 1024; d += 32) acc += mr[d] * rc_b[d];
#pragma unroll
    for (int o = 16; o > 0; o >>= 1) acc += __shfl_xor_sync(0xffffffffu, acc, o);
    if (lane == 0) g_cvec[e] = acc;
}

// --------------------------------------------------------------------------
// U GEMM (tensor, NT): out[b,t,:] = x[b,t,:] @ P^T + c,  t=1..2047.
// Row rg in [0,16376): b=rg/2047, t=1+rg%2047.
// CTA tile 64x128, 256 threads (8 warps 2x4), warp tile 32x32, k-chunk 32.
__global__ void __launch_bounds__(256)
k_nt_u(const float* __restrict__ x, float* __restrict__ out)
{
    // union: staging (As 64x36 + Bs 128x36 = 6912 floats) vs Cs (64x132 = 8448)
    __shared__ __align__(16) float sm[64 * 132];
    float (*As)[36]  = (float(*)[36])sm;
    float (*Bs)[36]  = (float(*)[36])(sm + 64 * 36);
    float (*Cs)[132] = (float(*)[132])sm;

    const int tid  = threadIdx.x;
    const int warp = tid >> 5;
    const int wr   = warp >> 2, wc = warp & 3;
    const int row0 = blockIdx.y * 64, col0 = blockIdx.x * 128;

    frag_c_t acc[2][2];
#pragma unroll
    for (int i = 0; i < 2; i++)
#pragma unroll
        for (int j = 0; j < 2; j++) wmma::fill_fragment(acc[i][j], 0.f);

    // per-thread A row pointers (2 staged rows)
    const float* arow[2];
#pragma unroll
    for (int l = 0; l < 2; l++) {
        int id = tid + l * 256;
        int r = id >> 3;
        int rg = row0 + r;
        if (rg < NROW_U) {
            int b = rg / 2047, t = 1 + rg % 2047;
            arow[l] = x + ((size_t)(b * 2048 + t)) * 1024;
        } else arow[l] = x;
    }

    for (int k0 = 0; k0 < 1024; k0 += 32) {
#pragma unroll
        for (int l = 0; l < 2; l++) {          // A: 512 float4
            int id = tid + l * 256;
            int r = id >> 3, c4 = (id & 7) * 4;
            *(float4*)&As[r][c4] = *(const float4*)(arow[l] + k0 + c4);
        }
#pragma unroll
        for (int l = 0; l < 4; l++) {          // B (g_P rows = output cols): 1024 float4
            int id = tid + l * 256;
            int n = id >> 3, c4 = (id & 7) * 4;
            *(float4*)&Bs[n][c4] =
                *(const float4*)(g_P + (size_t)(col0 + n) * 1024 + k0 + c4);
        }
        __syncthreads();
#pragma unroll
        for (int kk = 0; kk < 4; kk++) {
            frag_a_t araw, ahi[2], alo[2];
            frag_bc_t braw, bhi[2], blo[2];
#pragma unroll
            for (int i = 0; i < 2; i++) {
                wmma::load_matrix_sync(araw, &As[wr * 32 + i * 16][kk * 8], 36);
                split_tf32(araw, ahi[i], alo[i]);
            }
#pragma unroll
            for (int j = 0; j < 2; j++) {
                wmma::load_matrix_sync(braw, &Bs[wc * 32 + j * 16][kk * 8], 36);
                split_tf32(braw, bhi[j], blo[j]);
            }
#pragma unroll
            for (int i = 0; i < 2; i++)
#pragma unroll
                for (int j = 0; j < 2; j++) {
                    wmma::mma_sync(acc[i][j], ahi[i], bhi[j], acc[i][j]);
                    wmma::mma_sync(acc[i][j], alo[i], bhi[j], acc[i][j]);
                    wmma::mma_sync(acc[i][j], ahi[i], blo[j], acc[i][j]);
                }
        }
        __syncthreads();
    }
    // bounce through smem, then scatter with +c
#pragma unroll
    for (int i = 0; i < 2; i++)
#pragma unroll
        for (int j = 0; j < 2; j++)
            wmma::store_matrix_sync(&Cs[wr * 32 + i * 16][wc * 32 + j * 16],
                                    acc[i][j], 132, wmma::mem_row_major);
    __syncthreads();
#pragma unroll
    for (int l = 0; l < 8; l++) {              // 2048 float4
        int id = tid + l * 256;
        int r = id >> 5, c4 = (id & 31) * 4;
        int rg = row0 + r;
        if (rg < NROW_U) {
            int b = rg / 2047, t = 1 + rg % 2047;
            float4 v = *(float4*)&Cs[r][c4];
            int col = col0 + c4;
            v.x += g_cvec[col + 0]; v.y += g_cvec[col + 1];
            v.z += g_cvec[col + 2]; v.w += g_cvec[col + 3];
            *(float4*)(out + ((size_t)(b * 2048 + t)) * 1024 + col) = v;
        }
    }
}

// --------------------------------------------------------------------------
// out[b,0,:] = x[b,0,:] ; C[0] = y_0
__global__ void k_init(const float* __restrict__ x, float* __restrict__ out)
{
    int idx = blockIdx.x * blockDim.x + threadIdx.x;   // 8192
    int b = idx >> 10, e = idx & 1023;
    float v = x[((size_t)b * 2048) * 1024 + e];
    out[((size_t)b * 2048) * 1024 + e] = v;
    g_Cst[idx] = v;
}

// --------------------------------------------------------------------------
// Pass 1 step s (tensor, NT vs g_Q): w <- Q @ w + u_{32k+s}, chunks 0..62.
// CTA tile 32x64, 64 threads (2 warps side by side), warp tile 32x32.
__global__ void __launch_bounds__(64)
k_pass1(const float* __restrict__ u, int s)
{
    const float* Win = (s & 1) ? g_W0 : g_W1;
    float* Wout      = (s & 1) ? g_W1 : g_W0;

    __shared__ __align__(16) float As[32][36];
    __shared__ __align__(16) float Bs[64][36];
    __shared__ __align__(16) float Cs[32][68];

    const int tid  = threadIdx.x;
    const int wc   = tid >> 5;                 // warp 0/1 -> col half
    const int row0 = blockIdx.y * 32, col0 = blockIdx.x * 64;

    frag_c_t acc[2][2];
#pragma unroll
    for (int i = 0; i < 2; i++)
#pragma unroll
        for (int j = 0; j < 2; j++) wmma::fill_fragment(acc[i][j], 0.f);

    if (s > 1) {
        const float* arow[4];
#pragma unroll
        for (int l = 0; l < 4; l++) {
            int id = tid + l * 64;
            int r = id >> 3;
            int rg = row0 + r;
            arow[l] = (rg < R1) ? (Win + (size_t)rg * 1024) : Win;
        }
        for (int k0 = 0; k0 < 1024; k0 += 32) {
#pragma unroll
            for (int l = 0; l < 4; l++) {      // A: 256 float4
                int id = tid + l * 64;
                int r = id >> 3, c4 = (id & 7) * 4;
                *(float4*)&As[r][c4] = *(const float4*)(arow[l] + k0 + c4);
            }
#pragma unroll
            for (int l = 0; l < 8; l++) {      // B (g_Q rows): 512 float4
                int id = tid + l * 64;
                int n = id >> 3, c4 = (id & 7) * 4;
                *(float4*)&Bs[n][c4] =
                    *(const float4*)(g_Q + (size_t)(col0 + n) * 1024 + k0 + c4);
            }
            __syncthreads();
#pragma unroll
            for (int kk = 0; kk < 4; kk++) {
                frag_a_t araw, ahi[2], alo[2];
                frag_bc_t braw, bhi[2], blo[2];
#pragma unroll
                for (int i = 0; i < 2; i++) {
                    wmma::load_matrix_sync(araw, &As[i * 16][kk * 8], 36);
                    split_tf32(araw, ahi[i], alo[i]);
                }
#pragma unroll
                for (int j = 0; j < 2; j++) {
                    wmma::load_matrix_sync(braw, &Bs[wc * 32 + j * 16][kk * 8], 36);
                    split_tf32(braw, bhi[j], blo[j]);
                }
#pragma unroll
                for (int i = 0; i < 2; i++)
#pragma unroll
                    for (int j = 0; j < 2; j++) {
                        wmma::mma_sync(acc[i][j], ahi[i], bhi[j], acc[i][j]);
                        wmma::mma_sync(acc[i][j], alo[i], bhi[j], acc[i][j]);
                        wmma::mma_sync(acc[i][j], ahi[i], blo[j], acc[i][j]);
                    }
            }
            __syncthreads();
        }
    }
#pragma unroll
    for (int i = 0; i < 2; i++)
#pragma unroll
        for (int j = 0; j < 2; j++)
            wmma::store_matrix_sync(&Cs[i * 16][wc * 32 + j * 16],
                                    acc[i][j], 68, wmma::mem_row_major);
    __syncthreads();
#pragma unroll
    for (int l = 0; l < 8; l++) {              // 512 float4
        int id = tid + l * 64;
        int r = id >> 4, c4 = (id & 15) * 4;
        int rg = row0 + r;
        if (rg < R1) {
            int ch = rg >> 3, b = rg & 7;
            int t = ch * SCH + s;
            int col = col0 + c4;
            float4 uv = *(const float4*)(u + ((size_t)(b * 2048 + t)) * 1024 + col);
            float4 av = *(float4*)&Cs[r][c4];
            av.x += uv.x; av.y += uv.y; av.z += uv.z; av.w += uv.w;
            *(float4*)(Wout + (size_t)rg * 1024 + col) = av;
        }
    }
}

// --------------------------------------------------------------------------
// Carry chain: C[k] = W_end[k-1] + Q^32 @ C[k-1]. W_end = g_W0 (s=32 even).
__global__ void k_carry(int k)
{
    int warp = threadIdx.x >> 5;
    int lane = threadIdx.x & 31;
    const float* cprev = g_Cst + (size_t)(k - 1) * 8192;
    const float* wrow  = g_W0 + (size_t)(k - 1) * 8192;
#pragma unroll
    for (int r = 0; r < 2; r++) {
        int e = blockIdx.x * 16 + warp * 2 + r;
        const float* qrow = g_QS + (size_t)e * 1024;
#pragma unroll
        for (int b = 0; b < 8; b++) {
            float acc = 0.f;
            const float* cp = cprev + b * 1024;
#pragma unroll 4
            for (int d = lane; d < 1024; d += 32) acc += qrow[d] * cp[d];
#pragma unroll
            for (int o = 16; o > 0; o >>= 1) acc += __shfl_xor_sync(0xffffffffu, acc, o);
            if (lane == 0)
                g_Cst[(size_t)k * 8192 + b * 1024 + e] = wrow[b * 1024 + e] + acc;
        }
    }
}

// --------------------------------------------------------------------------
// Pass 2 step s (tensor, NT vs g_Q): y_{32k+s} = u + Q y_{32k+s-1}, in place.
// s==1 seeds from g_Cst; chunk 63 t=2048 skipped.
__global__ void __launch_bounds__(64)
k_pass2(float* __restrict__ y, int s)
{
    __shared__ __align__(16) float As[32][36];
    __shared__ __align__(16) float Bs[64][36];
    __shared__ __align__(16) float Cs[32][68];

    const int tid  = threadIdx.x;
    const int wc   = tid >> 5;
    const int row0 = blockIdx.y * 32, col0 = blockIdx.x * 64;

    frag_c_t acc[2][2];
#pragma unroll
    for (int i = 0; i < 2; i++)
#pragma unroll
        for (int j = 0; j < 2; j++) wmma::fill_fragment(acc[i][j], 0.f);

    const float* arow[4];
#pragma unroll
    for (int l = 0; l < 4; l++) {
        int id = tid + l * 64;
        int r = id >> 3;
        int rg = row0 + r;                     // < 512 always
        int ch = rg >> 3, b = rg & 7;
        int t = ch * SCH + s;
        arow[l] = (s == 1) ? (g_Cst + (size_t)rg * 1024)
                           : (y + ((size_t)(b * 2048 + t - 1)) * 1024);
    }

    for (int k0 = 0; k0 < 1024; k0 += 32) {
#pragma unroll
        for (int l = 0; l < 4; l++) {
            int id = tid + l * 64;
            int r = id >> 3, c4 = (id & 7) * 4;
            *(float4*)&As[r][c4] = *(const float4*)(arow[l] + k0 + c4);
        }
#pragma unroll
        for (int l = 0; l < 8; l++) {
            int id = tid + l * 64;
            int n = id >> 3, c4 = (id & 7) * 4;
            *(float4*)&Bs[n][c4] =
                *(const float4*)(g_Q + (size_t)(col0 + n) * 1024 + k0 + c4);
        }
        __syncthreads();
#pragma unroll
        for (int kk = 0; kk < 4; kk++) {
            frag_a_t araw, ahi[2], alo[2];
            frag_bc_t braw, bhi[2], blo[2];
#pragma unroll
            for (int i = 0; i < 2; i++) {
                wmma::load_matrix_sync(araw, &As[i * 16][kk * 8], 36);
                split_tf32(araw, ahi[i], alo[i]);
            }
#pragma unroll
            for (int j = 0; j < 2; j++) {
                wmma::load_matrix_sync(braw, &Bs[wc * 32 + j * 16][kk * 8], 36);
                split_tf32(braw, bhi[j], blo[j]);
            }
#pragma unroll
            for (int i = 0; i < 2; i++)
#pragma unroll
                for (int j = 0; j < 2; j++) {
                    wmma::mma_sync(acc[i][j], ahi[i], bhi[j], acc[i][j]);
                    wmma::mma_sync(acc[i][j], alo[i], bhi[j], acc[i][j]);
                    wmma::mma_sync(acc[i][j], ahi[i], blo[j], acc[i][j]);
                }
        }
        __syncthreads();
    }
#pragma unroll
    for (int i = 0; i < 2; i++)
#pragma unroll
        for (int j = 0; j < 2; j++)
            wmma::store_matrix_sync(&Cs[i * 16][wc * 32 + j * 16],
                                    acc[i][j], 68, wmma::mem_row_major);
    __syncthreads();
#pragma unroll
    for (int l = 0; l < 8; l++) {
        int id = tid + l * 64;
        int r = id >> 4, c4 = (id & 15) * 4;
        int rg = row0 + r;
        int ch = rg >> 3, b = rg & 7;
        int t = ch * SCH + s;
        if (t < LSEQ) {
            float* yp = y + ((size_t)(b * 2048 + t)) * 1024 + col0 + c4;
            float4 yv = *(float4*)yp;
            float4 av = *(float4*)&Cs[r][c4];
            yv.x += av.x; yv.y += av.y; yv.z += av.z; yv.w += av.w;
            *(float4*)yp = yv;
        }
    }
}

// --------------------------------------------------------------------------
extern "C" void kernel_launch(void* const* d_in, const int* in_sizes, int n_in,
                              void* d_out, int out_size)
{
    const float* x    = (const float*)d_in[0];
    const float* A_w  = (const float*)d_in[1];
    const float* C_w  = (const float*)d_in[2];
    const float* rc_w = (const float*)d_in[3];
    const float* rc_b = (const float*)d_in[4];
    float* out = (float*)d_out;

    dim3 gsq(16, 16);       // 1024x1024 NN: 16x16 tiles of 64x64

    k_prep_wy<<<4096, 256>>>(rc_w);
    // M = C_w @ A_w
    k_nn<<<gsq, 128>>>(C_w, A_w, -1, -1, BUF_M, 1024);
    // P = M @ Wx (Wx = rc_w[:, :1024], ldb = 3072)
    k_nn<<<gsq, 128>>>(0, rc_w, BUF_M, -1, BUF_P, 3072);
    // Q = M @ Wy
    k_nn<<<gsq, 128>>>(0, 0, BUF_M, BUF_WY, BUF_Q, 1024);
    // c = M @ rc_b
    k_matvec_c<<<128, 256>>>(rc_b);
    // U into d_out (t = 1..2047)
    k_nt_u<<<dim3(8, 256), 256>>>(x, out);
    // Q^32 via 5 squarings
    k_nn<<<gsq, 128>>>(0, 0, BUF_Q,  BUF_Q,  BUF_T1, 1024);
    k_nn<<<gsq, 128>>>(0, 0, BUF_T1, BUF_T1, BUF_T2, 1024);
    k_nn<<<gsq, 128>>>(0, 0, BUF_T2, BUF_T2, BUF_T1, 1024);
    k_nn<<<gsq, 128>>>(0, 0, BUF_T1, BUF_T1, BUF_T2, 1024);
    k_nn<<<gsq, 128>>>(0, 0, BUF_T2, BUF_T2, BUF_QS, 1024);
    // y_0 / C[0]
    k_init<<<32, 256>>>(x, out);
    // pass 1
    for (int s = 1; s <= SCH; s++)
        k_pass1<<<dim3(16, 16), 64>>>(out, s);
    // carry chain
    for (int k = 1; k < NCH; k++)
        k_carry<<<64, 256>>>(k);
    // pass 2
    for (int s = 1; s <= SCH; s++)
        k_pass2<<<dim3(16, 16), 64>>>(out, s);
}

// round 9
// speedup vs baseline: 1.5184x; 1.5184x over previous
#include <cuda_runtime.h>
#include <cuda_bf16.h>
#include <mma.h>
#include <cstddef>

using namespace nvcuda;

// ---------------------------------------------------------------------------
// S4Layer: B=8, L=2048, D=1024
//   M = C_w @ A_w ; P = M @ Wx ; Q = M @ Wy ; c = M @ rc_b
//   u_t = x[:,t] @ P^T + c   (t = 1..2047)
//   y_0 = x[:,0] ;  y_t = u_t + Q y_{t-1}
// Chunked scan: 64 chunks of S=32 (two passes + carry chain).
// GEMMs: bf16 tensor MMA (m16n16k16) with 2-term split (3 MMAs:
// hi*hi + lo*hi + hi*lo). Static operands P/Q pre-split to bf16 once;
// dynamic A-side split happens at smem staging time (not per fragment).
// ---------------------------------------------------------------------------

#define DM 1024
#define NB 8
#define LSEQ 2048
#define SCH 32
#define NCH 64
#define R1 504   // pass-1 rows = 63 chunks * 8 batch
#define NROW_U (NB * (LSEQ - 1))   // 16376

__device__ float g_M [DM * DM];
__device__ float g_P [DM * DM];
__device__ float g_Q [DM * DM];
__device__ float g_Wy[DM * DM];
__device__ float g_T1[DM * DM];
__device__ float g_T2[DM * DM];
__device__ float g_QS[DM * DM];
__device__ float g_cvec[DM];
__device__ float g_W0[R1 * DM];
__device__ float g_W1[R1 * DM];
__device__ float g_Cst[NCH * NB * DM];

// pre-split bf16 copies of P and Q (hi + lo)
__device__ __nv_bfloat16 g_Ph[DM * DM];
__device__ __nv_bfloat16 g_Pl[DM * DM];
__device__ __nv_bfloat16 g_Qh[DM * DM];
__device__ __nv_bfloat16 g_Ql[DM * DM];

#define BUF_M  0
#define BUF_P  1
#define BUF_Q  2
#define BUF_WY 3
#define BUF_T1 4
#define BUF_T2 5
#define BUF_QS 6

__device__ __forceinline__ float* sel_buf(int i)
{
    switch (i) {
        case BUF_M:  return g_M;
        case BUF_P:  return g_P;
        case BUF_Q:  return g_Q;
        case BUF_WY: return g_Wy;
        case BUF_T1: return g_T1;
        case BUF_T2: return g_T2;
        default:     return g_QS;
    }
}

typedef wmma::fragment<wmma::matrix_a, 16, 16, 16, __nv_bfloat16, wmma::row_major> bfa_t;
typedef wmma::fragment<wmma::matrix_b, 16, 16, 16, __nv_bfloat16, wmma::col_major> bfbc_t;
typedef wmma::fragment<wmma::matrix_b, 16, 16, 16, __nv_bfloat16, wmma::row_major> bfbr_t;
typedef wmma::fragment<wmma::accumulator, 16, 16, 16, float> bfc_t;

__device__ __forceinline__ void bsplit(float v, __nv_bfloat16& h, __nv_bfloat16& l)
{
    __nv_bfloat16 hb = __float2bfloat16(v);
    h = hb;
    l = __float2bfloat16(v - __bfloat162float(hb));
}

// --------------------------------------------------------------------------
// Wy[k][d] = rc_w[k, D+d] + rc_w[k, 2D+d]
__global__ void k_prep_wy(const float* __restrict__ rc_w)
{
    int idx = blockIdx.x * blockDim.x + threadIdx.x;   // 1M
    int k = idx >> 10, d = idx & 1023;
    g_Wy[idx] = rc_w[k * 3072 + 1024 + d] + rc_w[k * 3072 + 2048 + d];
}

// --------------------------------------------------------------------------
// Split fp32 matrix into bf16 hi/lo. which: 0 = P, 1 = Q.
__global__ void k_split(int which)
{
    int idx = blockIdx.x * blockDim.x + threadIdx.x;   // 1M
    float v = which ? g_Q[idx] : g_P[idx];
    __nv_bfloat16 h, l;
    bsplit(v, h, l);
    if (which) { g_Qh[idx] = h; g_Ql[idx] = l; }
    else       { g_Ph[idx] = h; g_Pl[idx] = l; }
}

// --------------------------------------------------------------------------
// NN GEMM (bf16 tensor): C[1024,1024] = A @ B (row-major, B ld = ldb).
// CTA tile 64x64, 128 threads (4 warps 2x2), k-chunk 32.
// A and B split to bf16 hi/lo at staging time.
__global__ void __launch_bounds__(128)
k_nn(const float* extA, const float* extB, int ia, int ib, int ic, int ldb)
{
    const float* A  = (ia >= 0) ? sel_buf(ia) : extA;
    const float* Bm = (ib >= 0) ? sel_buf(ib) : extB;
    float*       Cm = sel_buf(ic);

    __shared__ __align__(16) __nv_bfloat16 Ah[64][40];
    __shared__ __align__(16) __nv_bfloat16 Al[64][40];
    __shared__ __align__(16) __nv_bfloat16 Bh[32][72];
    __shared__ __align__(16) __nv_bfloat16 Bl[32][72];

    const int tid  = threadIdx.x;
    const int warp = tid >> 5;
    const int wr   = warp >> 1, wc = warp & 1;
    const int row0 = blockIdx.y * 64, col0 = blockIdx.x * 64;

    bfc_t acc[2][2];
#pragma unroll
    for (int i = 0; i < 2; i++)
#pragma unroll
        for (int j = 0; j < 2; j++) wmma::fill_fragment(acc[i][j], 0.f);

    for (int k0 = 0; k0 < 1024; k0 += 32) {
#pragma unroll
        for (int l = 0; l < 4; l++) {          // A: 64x32 floats
            int id = tid + l * 128;
            int r = id >> 3, c4 = (id & 7) * 4;
            float4 v = *(const float4*)(A + (size_t)(row0 + r) * 1024 + k0 + c4);
            bsplit(v.x, Ah[r][c4 + 0], Al[r][c4 + 0]);
            bsplit(v.y, Ah[r][c4 + 1], Al[r][c4 + 1]);
            bsplit(v.z, Ah[r][c4 + 2], Al[r][c4 + 2]);
            bsplit(v.w, Ah[r][c4 + 3], Al[r][c4 + 3]);
        }
#pragma unroll
        for (int l = 0; l < 4; l++) {          // B: 32x64 floats (k-major rows)
            int id = tid + l * 128;
            int k = id >> 4, n4 = (id & 15) * 4;
            float4 v = *(const float4*)(Bm + (size_t)(k0 + k) * ldb + col0 + n4);
            bsplit(v.x, Bh[k][n4 + 0], Bl[k][n4 + 0]);
            bsplit(v.y, Bh[k][n4 + 1], Bl[k][n4 + 1]);
            bsplit(v.z, Bh[k][n4 + 2], Bl[k][n4 + 2]);
            bsplit(v.w, Bh[k][n4 + 3], Bl[k][n4 + 3]);
        }
        __syncthreads();
#pragma unroll
        for (int kk = 0; kk < 2; kk++) {
            bfa_t ah[2], al[2];
            bfbr_t bh[2], bl[2];
#pragma unroll
            for (int i = 0; i < 2; i++) {
                wmma::load_matrix_sync(ah[i], &Ah[wr * 32 + i * 16][kk * 16], 40);
                wmma::load_matrix_sync(al[i], &Al[wr * 32 + i * 16][kk * 16], 40);
            }
#pragma unroll
            for (int j = 0; j < 2; j++) {
                wmma::load_matrix_sync(bh[j], &Bh[kk * 16][wc * 32 + j * 16], 72);
                wmma::load_matrix_sync(bl[j], &Bl[kk * 16][wc * 32 + j * 16], 72);
            }
#pragma unroll
            for (int i = 0; i < 2; i++)
#pragma unroll
                for (int j = 0; j < 2; j++) {
                    wmma::mma_sync(acc[i][j], ah[i], bh[j], acc[i][j]);
                    wmma::mma_sync(acc[i][j], al[i], bh[j], acc[i][j]);
                    wmma::mma_sync(acc[i][j], ah[i], bl[j], acc[i][j]);
                }
        }
        __syncthreads();
    }
#pragma unroll
    for (int i = 0; i < 2; i++)
#pragma unroll
        for (int j = 0; j < 2; j++)
            wmma::store_matrix_sync(
                Cm + (size_t)(row0 + wr * 32 + i * 16) * 1024 + col0 + wc * 32 + j * 16,
                acc[i][j], 1024, wmma::mem_row_major);
}

// --------------------------------------------------------------------------
// g_cvec[e] = sum_k g_M[e,k] * rc_b[k]
__global__ void k_matvec_c(const float* __restrict__ rc_b)
{
    int e = blockIdx.x * 8 + (threadIdx.x >> 5);
    int lane = threadIdx.x & 31;
    const float* mr = g_M + (size_t)e * 1024;
    float acc = 0.f;
#pragma unroll 4
    for (int d = lane; d < 1024; d += 32) acc += mr[d] * rc_b[d];
#pragma unroll
    for (int o = 16; o > 0; o >>= 1) acc += __shfl_xor_sync(0xffffffffu, acc, o);
    if (lane == 0) g_cvec[e] = acc;
}

// --------------------------------------------------------------------------
// U GEMM (bf16, NT): out[b,t,:] = x[b,t,:] @ P^T + c, t=1..2047.
// CTA tile 64x128, 256 threads (8 warps 2x4). B = pre-split g_Ph/g_Pl.
__global__ void __launch_bounds__(256)
k_nt_u(const float* __restrict__ x, float* __restrict__ out)
{
    __shared__ __align__(16) char sm[64 * 132 * 4];   // 33792 B (union)
    __nv_bfloat16 (*Ah)[40] = (__nv_bfloat16(*)[40])(sm);
    __nv_bfloat16 (*Al)[40] = (__nv_bfloat16(*)[40])(sm + 5120);
    __nv_bfloat16 (*Bh)[40] = (__nv_bfloat16(*)[40])(sm + 10240);
    __nv_bfloat16 (*Bl)[40] = (__nv_bfloat16(*)[40])(sm + 20480);
    float (*Cs)[132]        = (float(*)[132])(sm);

    const int tid  = threadIdx.x;
    const int warp = tid >> 5;
    const int wr   = warp >> 2, wc = warp & 3;
    const int row0 = blockIdx.y * 64, col0 = blockIdx.x * 128;

    bfc_t acc[2][2];
#pragma unroll
    for (int i = 0; i < 2; i++)
#pragma unroll
        for (int j = 0; j < 2; j++) wmma::fill_fragment(acc[i][j], 0.f);

    const float* arow[2];
#pragma unroll
    for (int l = 0; l < 2; l++) {
        int id = tid + l * 256;
        int r = id >> 3;
        int rg = row0 + r;
        if (rg < NROW_U) {
            int b = rg / 2047, t = 1 + rg % 2047;
            arow[l] = x + ((size_t)(b * 2048 + t)) * 1024;
        } else arow[l] = x;
    }

    for (int k0 = 0; k0 < 1024; k0 += 32) {
#pragma unroll
        for (int l = 0; l < 2; l++) {          // A: 64x32 floats, split
            int id = tid + l * 256;
            int r = id >> 3, c4 = (id & 7) * 4;
            float4 v = *(const float4*)(arow[l] + k0 + c4);
            bsplit(v.x, Ah[r][c4 + 0], Al[r][c4 + 0]);
            bsplit(v.y, Ah[r][c4 + 1], Al[r][c4 + 1]);
            bsplit(v.z, Ah[r][c4 + 2], Al[r][c4 + 2]);
            bsplit(v.w, Ah[r][c4 + 3], Al[r][c4 + 3]);
        }
#pragma unroll
        for (int l = 0; l < 2; l++) {          // B: 128 rows x 32 k bf16 (x2 arrays)
            int id = tid + l * 256;
            int n = id >> 2, kq = (id & 3) * 8;
            size_t off = (size_t)(col0 + n) * 1024 + k0 + kq;
            *(float4*)&Bh[n][kq] = *(const float4*)(g_Ph + off);
            *(float4*)&Bl[n][kq] = *(const float4*)(g_Pl + off);
        }
        __syncthreads();
#pragma unroll
        for (int kk = 0; kk < 2; kk++) {
            bfa_t ah[2], al[2];
            bfbc_t bh[2], bl[2];
#pragma unroll
            for (int i = 0; i < 2; i++) {
                wmma::load_matrix_sync(ah[i], &Ah[wr * 32 + i * 16][kk * 16], 40);
                wmma::load_matrix_sync(al[i], &Al[wr * 32 + i * 16][kk * 16], 40);
            }
#pragma unroll
            for (int j = 0; j < 2; j++) {
                wmma::load_matrix_sync(bh[j], &Bh[wc * 32 + j * 16][kk * 16], 40);
                wmma::load_matrix_sync(bl[j], &Bl[wc * 32 + j * 16][kk * 16], 40);
            }
#pragma unroll
            for (int i = 0; i < 2; i++)
#pragma unroll
                for (int j = 0; j < 2; j++) {
                    wmma::mma_sync(acc[i][j], ah[i], bh[j], acc[i][j]);
                    wmma::mma_sync(acc[i][j], al[i], bh[j], acc[i][j]);
                    wmma::mma_sync(acc[i][j], ah[i], bl[j], acc[i][j]);
                }
        }
        __syncthreads();
    }
    // bounce through smem (reuses staging space), then scatter with +c
#pragma unroll
    for (int i = 0; i < 2; i++)
#pragma unroll
        for (int j = 0; j < 2; j++)
            wmma::store_matrix_sync(&Cs[wr * 32 + i * 16][wc * 32 + j * 16],
                                    acc[i][j], 132, wmma::mem_row_major);
    __syncthreads();
#pragma unroll
    for (int l = 0; l < 8; l++) {
        int id = tid + l * 256;
        int r = id >> 5, c4 = (id & 31) * 4;
        int rg = row0 + r;
        if (rg < NROW_U) {
            int b = rg / 2047, t = 1 + rg % 2047;
            float4 v = *(float4*)&Cs[r][c4];
            int col = col0 + c4;
            v.x += g_cvec[col + 0]; v.y += g_cvec[col + 1];
            v.z += g_cvec[col + 2]; v.w += g_cvec[col + 3];
            *(float4*)(out + ((size_t)(b * 2048 + t)) * 1024 + col) = v;
        }
    }
}

// --------------------------------------------------------------------------
// out[b,0,:] = x[b,0,:] ; C[0] = y_0
__global__ void k_init(const float* __restrict__ x, float* __restrict__ out)
{
    int idx = blockIdx.x * blockDim.x + threadIdx.x;   // 8192
    int b = idx >> 10, e = idx & 1023;
    float v = x[((size_t)b * 2048) * 1024 + e];
    out[((size_t)b * 2048) * 1024 + e] = v;
    g_Cst[idx] = v;
}

// --------------------------------------------------------------------------
// Pass 1 step s (bf16, NT vs g_Qh/g_Ql): w <- Q @ w + u_{32k+s}, chunks 0..62.
// CTA tile 32x64, 64 threads (2 warps).
__global__ void __launch_bounds__(64)
k_pass1(const float* __restrict__ u, int s)
{
    const float* Win = (s & 1) ? g_W0 : g_W1;
    float* Wout      = (s & 1) ? g_W1 : g_W0;

    __shared__ __align__(16) __nv_bfloat16 Ah[32][40];
    __shared__ __align__(16) __nv_bfloat16 Al[32][40];
    __shared__ __align__(16) __nv_bfloat16 Bh[64][40];
    __shared__ __align__(16) __nv_bfloat16 Bl[64][40];
    __shared__ __align__(16) float Cs[32][68];

    const int tid  = threadIdx.x;
    const int wc   = tid >> 5;
    const int row0 = blockIdx.y * 32, col0 = blockIdx.x * 64;

    bfc_t acc[2][2];
#pragma unroll
    for (int i = 0; i < 2; i++)
#pragma unroll
        for (int j = 0; j < 2; j++) wmma::fill_fragment(acc[i][j], 0.f);

    if (s > 1) {
        const float* arow[4];
#pragma unroll
        for (int l = 0; l < 4; l++) {
            int id = tid + l * 64;
            int r = id >> 3;
            int rg = row0 + r;
            arow[l] = (rg < R1) ? (Win + (size_t)rg * 1024) : Win;
        }
        for (int k0 = 0; k0 < 1024; k0 += 32) {
#pragma unroll
            for (int l = 0; l < 4; l++) {      // A: 32x32 floats, split
                int id = tid + l * 64;
                int r = id >> 3, c4 = (id & 7) * 4;
                float4 v = *(const float4*)(arow[l] + k0 + c4);
                bsplit(v.x, Ah[r][c4 + 0], Al[r][c4 + 0]);
                bsplit(v.y, Ah[r][c4 + 1], Al[r][c4 + 1]);
                bsplit(v.z, Ah[r][c4 + 2], Al[r][c4 + 2]);
                bsplit(v.w, Ah[r][c4 + 3], Al[r][c4 + 3]);
            }
#pragma unroll
            for (int l = 0; l < 4; l++) {      // B: 64 rows x 32 k bf16 (x2)
                int id = tid + l * 64;
                int n = id >> 2, kq = (id & 3) * 8;
                size_t off = (size_t)(col0 + n) * 1024 + k0 + kq;
                *(float4*)&Bh[n][kq] = *(const float4*)(g_Qh + off);
                *(float4*)&Bl[n][kq] = *(const float4*)(g_Ql + off);
            }
            __syncthreads();
#pragma unroll
            for (int kk = 0; kk < 2; kk++) {
                bfa_t ah[2], al[2];
                bfbc_t bh[2], bl[2];
#pragma unroll
                for (int i = 0; i < 2; i++) {
                    wmma::load_matrix_sync(ah[i], &Ah[i * 16][kk * 16], 40);
                    wmma::load_matrix_sync(al[i], &Al[i * 16][kk * 16], 40);
                }
#pragma unroll
                for (int j = 0; j < 2; j++) {
                    wmma::load_matrix_sync(bh[j], &Bh[wc * 32 + j * 16][kk * 16], 40);
                    wmma::load_matrix_sync(bl[j], &Bl[wc * 32 + j * 16][kk * 16], 40);
                }
#pragma unroll
                for (int i = 0; i < 2; i++)
#pragma unroll
                    for (int j = 0; j < 2; j++) {
                        wmma::mma_sync(acc[i][j], ah[i], bh[j], acc[i][j]);
                        wmma::mma_sync(acc[i][j], al[i], bh[j], acc[i][j]);
                        wmma::mma_sync(acc[i][j], ah[i], bl[j], acc[i][j]);
                    }
            }
            __syncthreads();
        }
    }
#pragma unroll
    for (int i = 0; i < 2; i++)
#pragma unroll
        for (int j = 0; j < 2; j++)
            wmma::store_matrix_sync(&Cs[i * 16][wc * 32 + j * 16],
                                    acc[i][j], 68, wmma::mem_row_major);
    __syncthreads();
#pragma unroll
    for (int l = 0; l < 8; l++) {
        int id = tid + l * 64;
        int r = id >> 4, c4 = (id & 15) * 4;
        int rg = row0 + r;
        if (rg < R1) {
            int ch = rg >> 3, b = rg & 7;
            int t = ch * SCH + s;
            int col = col0 + c4;
            float4 uv = *(const float4*)(u + ((size_t)(b * 2048 + t)) * 1024 + col);
            float4 av = *(float4*)&Cs[r][c4];
            av.x += uv.x; av.y += uv.y; av.z += uv.z; av.w += uv.w;
            *(float4*)(Wout + (size_t)rg * 1024 + col) = av;
        }
    }
}

// --------------------------------------------------------------------------
// Carry chain: C[k] = W_end[k-1] + Q^32 @ C[k-1]. W_end = g_W0 (s=32 even).
__global__ void k_carry(int k)
{
    int warp = threadIdx.x >> 5;
    int lane = threadIdx.x & 31;
    const float* cprev = g_Cst + (size_t)(k - 1) * 8192;
    const float* wrow  = g_W0 + (size_t)(k - 1) * 8192;
#pragma unroll
    for (int r = 0; r < 2; r++) {
        int e = blockIdx.x * 16 + warp * 2 + r;
        const float* qrow = g_QS + (size_t)e * 1024;
#pragma unroll
        for (int b = 0; b < 8; b++) {
            float acc = 0.f;
            const float* cp = cprev + b * 1024;
#pragma unroll 4
            for (int d = lane; d < 1024; d += 32) acc += qrow[d] * cp[d];
#pragma unroll
            for (int o = 16; o > 0; o >>= 1) acc += __shfl_xor_sync(0xffffffffu, acc, o);
            if (lane == 0)
                g_Cst[(size_t)k * 8192 + b * 1024 + e] = wrow[b * 1024 + e] + acc;
        }
    }
}

// --------------------------------------------------------------------------
// Pass 2 step s (bf16, NT vs g_Qh/g_Ql): y_{32k+s} = u + Q y_{32k+s-1}, in place.
__global__ void __launch_bounds__(64)
k_pass2(float* __restrict__ y, int s)
{
    __shared__ __align__(16) __nv_bfloat16 Ah[32][40];
    __shared__ __align__(16) __nv_bfloat16 Al[32][40];
    __shared__ __align__(16) __nv_bfloat16 Bh[64][40];
    __shared__ __align__(16) __nv_bfloat16 Bl[64][40];
    __shared__ __align__(16) float Cs[32][68];

    const int tid  = threadIdx.x;
    const int wc   = tid >> 5;
    const int row0 = blockIdx.y * 32, col0 = blockIdx.x * 64;

    bfc_t acc[2][2];
#pragma unroll
    for (int i = 0; i < 2; i++)
#pragma unroll
        for (int j = 0; j < 2; j++) wmma::fill_fragment(acc[i][j], 0.f);

    const float* arow[4];
#pragma unroll
    for (int l = 0; l < 4; l++) {
        int id = tid + l * 64;
        int r = id >> 3;
        int rg = row0 + r;                     // < 512 always
        int ch = rg >> 3, b = rg & 7;
        int t = ch * SCH + s;
        arow[l] = (s == 1) ? (g_Cst + (size_t)rg * 1024)
                           : (y + ((size_t)(b * 2048 + t - 1)) * 1024);
    }

    for (int k0 = 0; k0 < 1024; k0 += 32) {
#pragma unroll
        for (int l = 0; l < 4; l++) {
            int id = tid + l * 64;
            int r = id >> 3, c4 = (id & 7) * 4;
            float4 v = *(const float4*)(arow[l] + k0 + c4);
            bsplit(v.x, Ah[r][c4 + 0], Al[r][c4 + 0]);
            bsplit(v.y, Ah[r][c4 + 1], Al[r][c4 + 1]);
            bsplit(v.z, Ah[r][c4 + 2], Al[r][c4 + 2]);
            bsplit(v.w, Ah[r][c4 + 3], Al[r][c4 + 3]);
        }
#pragma unroll
        for (int l = 0; l < 4; l++) {
            int id = tid + l * 64;
            int n = id >> 2, kq = (id & 3) * 8;
            size_t off = (size_t)(col0 + n) * 1024 + k0 + kq;
            *(float4*)&Bh[n][kq] = *(const float4*)(g_Qh + off);
            *(float4*)&Bl[n][kq] = *(const float4*)(g_Ql + off);
        }
        __syncthreads();
#pragma unroll
        for (int kk = 0; kk < 2; kk++) {
            bfa_t ah[2], al[2];
            bfbc_t bh[2], bl[2];
#pragma unroll
            for (int i = 0; i < 2; i++) {
                wmma::load_matrix_sync(ah[i], &Ah[i * 16][kk * 16], 40);
                wmma::load_matrix_sync(al[i], &Al[i * 16][kk * 16], 40);
            }
#pragma unroll
            for (int j = 0; j < 2; j++) {
                wmma::load_matrix_sync(bh[j], &Bh[wc * 32 + j * 16][kk * 16], 40);
                wmma::load_matrix_sync(bl[j], &Bl[wc * 32 + j * 16][kk * 16], 40);
            }
#pragma unroll
            for (int i = 0; i < 2; i++)
#pragma unroll
                for (int j = 0; j < 2; j++) {
                    wmma::mma_sync(acc[i][j], ah[i], bh[j], acc[i][j]);
                    wmma::mma_sync(acc[i][j], al[i], bh[j], acc[i][j]);
                    wmma::mma_sync(acc[i][j], ah[i], bl[j], acc[i][j]);
                }
        }
        __syncthreads();
    }
#pragma unroll
    for (int i = 0; i < 2; i++)
#pragma unroll
        for (int j = 0; j < 2; j++)
            wmma::store_matrix_sync(&Cs[i * 16][wc * 32 + j * 16],
                                    acc[i][j], 68, wmma::mem_row_major);
    __syncthreads();
#pragma unroll
    for (int l = 0; l < 8; l++) {
        int id = tid + l * 64;
        int r = id >> 4, c4 = (id & 15) * 4;
        int rg = row0 + r;
        int ch = rg >> 3, b = rg & 7;
        int t = ch * SCH + s;
        if (t < LSEQ) {
            float* yp = y + ((size_t)(b * 2048 + t)) * 1024 + col0 + c4;
            float4 yv = *(float4*)yp;
            float4 av = *(float4*)&Cs[r][c4];
            yv.x += av.x; yv.y += av.y; yv.z += av.z; yv.w += av.w;
            *(float4*)yp = yv;
        }
    }
}

// --------------------------------------------------------------------------
extern "C" void kernel_launch(void* const* d_in, const int* in_sizes, int n_in,
                              void* d_out, int out_size)
{
    const float* x    = (const float*)d_in[0];
    const float* A_w  = (const float*)d_in[1];
    const float* C_w  = (const float*)d_in[2];
    const float* rc_w = (const float*)d_in[3];
    const float* rc_b = (const float*)d_in[4];
    float* out = (float*)d_out;

    dim3 gsq(16, 16);       // 1024x1024 NN: 16x16 tiles of 64x64

    k_prep_wy<<<4096, 256>>>(rc_w);
    // M = C_w @ A_w
    k_nn<<<gsq, 128>>>(C_w, A_w, -1, -1, BUF_M, 1024);
    // P = M @ Wx (Wx = rc_w[:, :1024], ldb = 3072)
    k_nn<<<gsq, 128>>>(0, rc_w, BUF_M, -1, BUF_P, 3072);
    // Q = M @ Wy
    k_nn<<<gsq, 128>>>(0, 0, BUF_M, BUF_WY, BUF_Q, 1024);
    // pre-split P, Q into bf16 hi/lo
    k_split<<<4096, 256>>>(0);
    k_split<<<4096, 256>>>(1);
    // c = M @ rc_b
    k_matvec_c<<<128, 256>>>(rc_b);
    // U into d_out (t = 1..2047)
    k_nt_u<<<dim3(8, 256), 256>>>(x, out);
    // Q^32 via 5 squarings
    k_nn<<<gsq, 128>>>(0, 0, BUF_Q,  BUF_Q,  BUF_T1, 1024);
    k_nn<<<gsq, 128>>>(0, 0, BUF_T1, BUF_T1, BUF_T2, 1024);
    k_nn<<<gsq, 128>>>(0, 0, BUF_T2, BUF_T2, BUF_T1, 1024);
    k_nn<<<gsq, 128>>>(0, 0, BUF_T1, BUF_T1, BUF_T2, 1024);
    k_nn<<<gsq, 128>>>(0, 0, BUF_T2, BUF_T2, BUF_QS, 1024);
    // y_0 / C[0]
    k_init<<<32, 256>>>(x, out);
    // pass 1
    for (int s = 1; s <= SCH; s++)
        k_pass1<<<dim3(16, 16), 64>>>(out, s);
    // carry chain
    for (int k = 1; k < NCH; k++)
        k_carry<<<64, 256>>>(k);
    // pass 2
    for (int s = 1; s <= SCH; s++)
        k_pass2<<<dim3(16, 16), 64>>>(out, s);
}

// round 10
// speedup vs baseline: 1.5847x; 1.0437x over previous
#include <cuda_runtime.h>
#include <cuda_bf16.h>
#include <mma.h>
#include <cstddef>

using namespace nvcuda;

// ---------------------------------------------------------------------------
// S4Layer: B=8, L=2048, D=1024. Chunked scan: 64 chunks of S=32.
// GEMMs: bf16 tensor MMA m16n16k16, 2-term split (hi*hi + lo*hi + hi*lo).
// Static operands (P, Q) and scan state carried in pre-split bf16 hi/lo;
// no fp32->bf16 conversion in any hot mainloop.
// ---------------------------------------------------------------------------

#define DM 1024
#define NB 8
#define LSEQ 2048
#define SCH 32
#define NCH 64
#define R1 504                     // pass-1 rows = 63 chunks * 8 batch
#define R2 512                     // pass-2 rows = 64 chunks * 8 batch
#define NROW_U (NB * (LSEQ - 1))   // 16376

__device__ float g_M [DM * DM];
__device__ float g_P [DM * DM];
__device__ float g_Q [DM * DM];
__device__ float g_Wy[DM * DM];
__device__ float g_T1[DM * DM];
__device__ float g_T2[DM * DM];
__device__ float g_QS[DM * DM];
__device__ float g_cvec[DM];
__device__ float g_W0[R1 * DM];            // fp32 chunk-end sums (for carries)
__device__ float g_Cst[NCH * NB * DM];     // fp32 carry states

// pre-split bf16 hi/lo operands and states
__device__ __nv_bfloat16 g_Ph[DM * DM],  g_Pl[DM * DM];
__device__ __nv_bfloat16 g_Qh[DM * DM],  g_Ql[DM * DM];
__device__ __nv_bfloat16 g_Xh[NB * LSEQ * DM], g_Xl[NB * LSEQ * DM];
__device__ __nv_bfloat16 g_Wsh[2][R1 * DM], g_Wsl[2][R1 * DM];  // pass1 state
__device__ __nv_bfloat16 g_Ysh[2][R2 * DM], g_Ysl[2][R2 * DM];  // pass2 state

#define BUF_M  0
#define BUF_P  1
#define BUF_Q  2
#define BUF_WY 3
#define BUF_T1 4
#define BUF_T2 5
#define BUF_QS 6

__device__ __forceinline__ float* sel_buf(int i)
{
    switch (i) {
        case BUF_M:  return g_M;
        case BUF_P:  return g_P;
        case BUF_Q:  return g_Q;
        case BUF_WY: return g_Wy;
        case BUF_T1: return g_T1;
        case BUF_T2: return g_T2;
        default:     return g_QS;
    }
}

typedef wmma::fragment<wmma::matrix_a, 16, 16, 16, __nv_bfloat16, wmma::row_major> bfa_t;
typedef wmma::fragment<wmma::matrix_b, 16, 16, 16, __nv_bfloat16, wmma::col_major> bfbc_t;
typedef wmma::fragment<wmma::matrix_b, 16, 16, 16, __nv_bfloat16, wmma::row_major> bfbr_t;
typedef wmma::fragment<wmma::accumulator, 16, 16, 16, float> bfc_t;

__device__ __forceinline__ void bsplit(float v, __nv_bfloat16& h, __nv_bfloat16& l)
{
    __nv_bfloat16 hb = __float2bfloat16(v);
    h = hb;
    l = __float2bfloat16(v - __bfloat162float(hb));
}

// --------------------------------------------------------------------------
__global__ void k_prep_wy(const float* __restrict__ rc_w)
{
    int idx = blockIdx.x * blockDim.x + threadIdx.x;   // 1M
    int k = idx >> 10, d = idx & 1023;
    g_Wy[idx] = rc_w[k * 3072 + 1024 + d] + rc_w[k * 3072 + 2048 + d];
}

// Split fp32 matrix into bf16 hi/lo. which: 0 = P, 1 = Q.
__global__ void k_split(int which)
{
    int idx = blockIdx.x * blockDim.x + threadIdx.x;   // 1M
    float v = which ? g_Q[idx] : g_P[idx];
    if (which) bsplit(v, g_Qh[idx], g_Ql[idx]);
    else       bsplit(v, g_Ph[idx], g_Pl[idx]);
}

// Split all of x into bf16 hi/lo.
__global__ void k_split_x(const float* __restrict__ x)
{
    int idx = blockIdx.x * blockDim.x + threadIdx.x;   // 16.7M
    bsplit(x[idx], g_Xh[idx], g_Xl[idx]);
}

// Split carry states into pass-2 seed state (buffer 1, read by s=1).
__global__ void k_seed()
{
    int idx = blockIdx.x * blockDim.x + threadIdx.x;   // 524288
    bsplit(g_Cst[idx], g_Ysh[1][idx], g_Ysl[1][idx]);
}

// --------------------------------------------------------------------------
// NN GEMM (bf16 tensor): C[1024,1024] = A @ B (row-major, B ld = ldb).
// CTA 64x64, 128 threads (4 warps 2x2); fp32 in, split at staging (cold path).
__global__ void __launch_bounds__(128)
k_nn(const float* extA, const float* extB, int ia, int ib, int ic, int ldb)
{
    const float* A  = (ia >= 0) ? sel_buf(ia) : extA;
    const float* Bm = (ib >= 0) ? sel_buf(ib) : extB;
    float*       Cm = sel_buf(ic);

    __shared__ __align__(16) __nv_bfloat16 Ah[64][40];
    __shared__ __align__(16) __nv_bfloat16 Al[64][40];
    __shared__ __align__(16) __nv_bfloat16 Bh[32][72];
    __shared__ __align__(16) __nv_bfloat16 Bl[32][72];

    const int tid  = threadIdx.x;
    const int warp = tid >> 5;
    const int wr   = warp >> 1, wc = warp & 1;
    const int row0 = blockIdx.y * 64, col0 = blockIdx.x * 64;

    bfc_t acc[2][2];
#pragma unroll
    for (int i = 0; i < 2; i++)
#pragma unroll
        for (int j = 0; j < 2; j++) wmma::fill_fragment(acc[i][j], 0.f);

    for (int k0 = 0; k0 < 1024; k0 += 32) {
#pragma unroll
        for (int l = 0; l < 4; l++) {
            int id = tid + l * 128;
            int r = id >> 3, c4 = (id & 7) * 4;
            float4 v = *(const float4*)(A + (size_t)(row0 + r) * 1024 + k0 + c4);
            bsplit(v.x, Ah[r][c4 + 0], Al[r][c4 + 0]);
            bsplit(v.y, Ah[r][c4 + 1], Al[r][c4 + 1]);
            bsplit(v.z, Ah[r][c4 + 2], Al[r][c4 + 2]);
            bsplit(v.w, Ah[r][c4 + 3], Al[r][c4 + 3]);
        }
#pragma unroll
        for (int l = 0; l < 4; l++) {
            int id = tid + l * 128;
            int k = id >> 4, n4 = (id & 15) * 4;
            float4 v = *(const float4*)(Bm + (size_t)(k0 + k) * ldb + col0 + n4);
            bsplit(v.x, Bh[k][n4 + 0], Bl[k][n4 + 0]);
            bsplit(v.y, Bh[k][n4 + 1], Bl[k][n4 + 1]);
            bsplit(v.z, Bh[k][n4 + 2], Bl[k][n4 + 2]);
            bsplit(v.w, Bh[k][n4 + 3], Bl[k][n4 + 3]);
        }
        __syncthreads();
#pragma unroll
        for (int kk = 0; kk < 2; kk++) {
            bfa_t ah[2], al[2];
            bfbr_t bh[2], bl[2];
#pragma unroll
            for (int i = 0; i < 2; i++) {
                wmma::load_matrix_sync(ah[i], &Ah[wr * 32 + i * 16][kk * 16], 40);
                wmma::load_matrix_sync(al[i], &Al[wr * 32 + i * 16][kk * 16], 40);
            }
#pragma unroll
            for (int j = 0; j < 2; j++) {
                wmma::load_matrix_sync(bh[j], &Bh[kk * 16][wc * 32 + j * 16], 72);
                wmma::load_matrix_sync(bl[j], &Bl[kk * 16][wc * 32 + j * 16], 72);
            }
#pragma unroll
            for (int i = 0; i < 2; i++)
#pragma unroll
                for (int j = 0; j < 2; j++) {
                    wmma::mma_sync(acc[i][j], ah[i], bh[j], acc[i][j]);
                    wmma::mma_sync(acc[i][j], al[i], bh[j], acc[i][j]);
                    wmma::mma_sync(acc[i][j], ah[i], bl[j], acc[i][j]);
                }
        }
        __syncthreads();
    }
#pragma unroll
    for (int i = 0; i < 2; i++)
#pragma unroll
        for (int j = 0; j < 2; j++)
            wmma::store_matrix_sync(
                Cm + (size_t)(row0 + wr * 32 + i * 16) * 1024 + col0 + wc * 32 + j * 16,
                acc[i][j], 1024, wmma::mem_row_major);
}

// --------------------------------------------------------------------------
__global__ void k_matvec_c(const float* __restrict__ rc_b)
{
    int e = blockIdx.x * 8 + (threadIdx.x >> 5);
    int lane = threadIdx.x & 31;
    const float* mr = g_M + (size_t)e * 1024;
    float acc = 0.f;
#pragma unroll 4
    for (int d = lane; d < 1024; d += 32) acc += mr[d] * rc_b[d];
#pragma unroll
    for (int o = 16; o > 0; o >>= 1) acc += __shfl_xor_sync(0xffffffffu, acc, o);
    if (lane == 0) g_cvec[e] = acc;
}

// --------------------------------------------------------------------------
// U GEMM (bf16, NT): out[b,t,:] = x[b,t,:] @ P^T + c, t=1..2047.
// CTA 64x128, 256 threads (8 warps 2x4). A from g_Xh/g_Xl, B from g_Ph/g_Pl.
__global__ void __launch_bounds__(256)
k_nt_u(float* __restrict__ out)
{
    __shared__ __align__(16) char sm[64 * 132 * 4];   // 33792 B union
    __nv_bfloat16 (*Ah)[40] = (__nv_bfloat16(*)[40])(sm);
    __nv_bfloat16 (*Al)[40] = (__nv_bfloat16(*)[40])(sm + 5120);
    __nv_bfloat16 (*Bh)[40] = (__nv_bfloat16(*)[40])(sm + 10240);
    __nv_bfloat16 (*Bl)[40] = (__nv_bfloat16(*)[40])(sm + 20480);
    float (*Cs)[132]        = (float(*)[132])(sm);

    const int tid  = threadIdx.x;
    const int warp = tid >> 5;
    const int wr   = warp >> 2, wc = warp & 3;
    const int row0 = blockIdx.y * 64, col0 = blockIdx.x * 128;

    bfc_t acc[2][2];
#pragma unroll
    for (int i = 0; i < 2; i++)
#pragma unroll
        for (int j = 0; j < 2; j++) wmma::fill_fragment(acc[i][j], 0.f);

    // A staging: each thread loads one float4 (=8 bf16) per buffer per k-chunk
    const int ar = tid >> 2, af = (tid & 3) * 8;
    size_t axoff;
    {
        int rg = row0 + ar;
        int b = 0, t = 0;
        if (rg < NROW_U) { b = rg / 2047; t = 1 + rg % 2047; }
        axoff = ((size_t)(b * 2048 + t)) * 1024;
    }

    for (int k0 = 0; k0 < 1024; k0 += 32) {
        *(float4*)&Ah[ar][af] = *(const float4*)(g_Xh + axoff + k0 + af);
        *(float4*)&Al[ar][af] = *(const float4*)(g_Xl + axoff + k0 + af);
#pragma unroll
        for (int l = 0; l < 2; l++) {
            int id = tid + l * 256;
            int n = id >> 2, f = (id & 3) * 8;
            size_t off = (size_t)(col0 + n) * 1024 + k0 + f;
            *(float4*)&Bh[n][f] = *(const float4*)(g_Ph + off);
            *(float4*)&Bl[n][f] = *(const float4*)(g_Pl + off);
        }
        __syncthreads();
#pragma unroll
        for (int kk = 0; kk < 2; kk++) {
            bfa_t ah[2], al[2];
            bfbc_t bh[2], bl[2];
#pragma unroll
            for (int i = 0; i < 2; i++) {
                wmma::load_matrix_sync(ah[i], &Ah[wr * 32 + i * 16][kk * 16], 40);
                wmma::load_matrix_sync(al[i], &Al[wr * 32 + i * 16][kk * 16], 40);
            }
#pragma unroll
            for (int j = 0; j < 2; j++) {
                wmma::load_matrix_sync(bh[j], &Bh[wc * 32 + j * 16][kk * 16], 40);
                wmma::load_matrix_sync(bl[j], &Bl[wc * 32 + j * 16][kk * 16], 40);
            }
#pragma unroll
            for (int i = 0; i < 2; i++)
#pragma unroll
                for (int j = 0; j < 2; j++) {
                    wmma::mma_sync(acc[i][j], ah[i], bh[j], acc[i][j]);
                    wmma::mma_sync(acc[i][j], al[i], bh[j], acc[i][j]);
                    wmma::mma_sync(acc[i][j], ah[i], bl[j], acc[i][j]);
                }
        }
        __syncthreads();
    }
#pragma unroll
    for (int i = 0; i < 2; i++)
#pragma unroll
        for (int j = 0; j < 2; j++)
            wmma::store_matrix_sync(&Cs[wr * 32 + i * 16][wc * 32 + j * 16],
                                    acc[i][j], 132, wmma::mem_row_major);
    __syncthreads();
#pragma unroll
    for (int l = 0; l < 8; l++) {
        int id = tid + l * 256;
        int r = id >> 5, c4 = (id & 31) * 4;
        int rg = row0 + r;
        if (rg < NROW_U) {
            int b = rg / 2047, t = 1 + rg % 2047;
            float4 v = *(float4*)&Cs[r][c4];
            int col = col0 + c4;
            v.x += g_cvec[col + 0]; v.y += g_cvec[col + 1];
            v.z += g_cvec[col + 2]; v.w += g_cvec[col + 3];
            *(float4*)(out + ((size_t)(b * 2048 + t)) * 1024 + col) = v;
        }
    }
}

// --------------------------------------------------------------------------
__global__ void k_init(const float* __restrict__ x, float* __restrict__ out)
{
    int idx = blockIdx.x * blockDim.x + threadIdx.x;   // 8192
    int b = idx >> 10, e = idx & 1023;
    float v = x[((size_t)b * 2048) * 1024 + e];
    out[((size_t)b * 2048) * 1024 + e] = v;
    g_Cst[idx] = v;
}

// --------------------------------------------------------------------------
// Pass 1 step s: w <- Q @ w + u_{32k+s}, chunks 0..62 (504 rows).
// CTA 64x64, 128 threads (4 warps). State in bf16 hi/lo, double-buffered.
__global__ void __launch_bounds__(128)
k_pass1(const float* __restrict__ u, int s)
{
    const int wb = s & 1, rb = wb ^ 1;
    const __nv_bfloat16* Wih = g_Wsh[rb];
    const __nv_bfloat16* Wil = g_Wsl[rb];
    __nv_bfloat16* Woh = g_Wsh[wb];
    __nv_bfloat16* Wol = g_Wsl[wb];

    __shared__ __align__(16) __nv_bfloat16 Ah[64][40];
    __shared__ __align__(16) __nv_bfloat16 Al[64][40];
    __shared__ __align__(16) __nv_bfloat16 Bh[64][40];
    __shared__ __align__(16) __nv_bfloat16 Bl[64][40];
    __shared__ __align__(16) float Cs[64][68];

    const int tid  = threadIdx.x;
    const int warp = tid >> 5;
    const int wr   = warp >> 1, wc = warp & 1;
    const int row0 = blockIdx.y * 64, col0 = blockIdx.x * 64;

    bfc_t acc[2][2];
#pragma unroll
    for (int i = 0; i < 2; i++)
#pragma unroll
        for (int j = 0; j < 2; j++) wmma::fill_fragment(acc[i][j], 0.f);

    if (s > 1) {
        for (int k0 = 0; k0 < 1024; k0 += 32) {
#pragma unroll
            for (int l = 0; l < 2; l++) {
                int id = tid + l * 128;
                int r = id >> 2, f = (id & 3) * 8;
                int rg = row0 + r;
                int rga = (rg < R1) ? rg : 0;
                size_t offa = (size_t)rga * 1024 + k0 + f;
                *(float4*)&Ah[r][f] = *(const float4*)(Wih + offa);
                *(float4*)&Al[r][f] = *(const float4*)(Wil + offa);
                size_t offb = (size_t)(col0 + r) * 1024 + k0 + f;
                *(float4*)&Bh[r][f] = *(const float4*)(g_Qh + offb);
                *(float4*)&Bl[r][f] = *(const float4*)(g_Ql + offb);
            }
            __syncthreads();
#pragma unroll
            for (int kk = 0; kk < 2; kk++) {
                bfa_t ah[2], al[2];
                bfbc_t bh[2], bl[2];
#pragma unroll
                for (int i = 0; i < 2; i++) {
                    wmma::load_matrix_sync(ah[i], &Ah[wr * 32 + i * 16][kk * 16], 40);
                    wmma::load_matrix_sync(al[i], &Al[wr * 32 + i * 16][kk * 16], 40);
                }
#pragma unroll
                for (int j = 0; j < 2; j++) {
                    wmma::load_matrix_sync(bh[j], &Bh[wc * 32 + j * 16][kk * 16], 40);
                    wmma::load_matrix_sync(bl[j], &Bl[wc * 32 + j * 16][kk * 16], 40);
                }
#pragma unroll
                for (int i = 0; i < 2; i++)
#pragma unroll
                    for (int j = 0; j < 2; j++) {
                        wmma::mma_sync(acc[i][j], ah[i], bh[j], acc[i][j]);
                        wmma::mma_sync(acc[i][j], al[i], bh[j], acc[i][j]);
                        wmma::mma_sync(acc[i][j], ah[i], bl[j], acc[i][j]);
                    }
            }
            __syncthreads();
        }
    }
#pragma unroll
    for (int i = 0; i < 2; i++)
#pragma unroll
        for (int j = 0; j < 2; j++)
            wmma::store_matrix_sync(&Cs[wr * 32 + i * 16][wc * 32 + j * 16],
                                    acc[i][j], 68, wmma::mem_row_major);
    __syncthreads();
#pragma unroll
    for (int l = 0; l < 8; l++) {
        int id = tid + l * 128;
        int r = id >> 4, c4 = (id & 15) * 4;
        int rg = row0 + r;
        if (rg < R1) {
            int ch = rg >> 3, b = rg & 7;
            int t = ch * SCH + s;
            int col = col0 + c4;
            float4 uv = *(const float4*)(u + ((size_t)(b * 2048 + t)) * 1024 + col);
            float4 av = *(float4*)&Cs[r][c4];
            av.x += uv.x; av.y += uv.y; av.z += uv.z; av.w += uv.w;
            size_t soff = (size_t)rg * 1024 + col;
            __nv_bfloat162 hh, ll;
            __nv_bfloat16 h, lo;
            bsplit(av.x, h, lo); hh.x = h; ll.x = lo;
            bsplit(av.y, h, lo); hh.y = h; ll.y = lo;
            *(__nv_bfloat162*)(Woh + soff)     = hh;
            *(__nv_bfloat162*)(Wol + soff)     = ll;
            bsplit(av.z, h, lo); hh.x = h; ll.x = lo;
            bsplit(av.w, h, lo); hh.y = h; ll.y = lo;
            *(__nv_bfloat162*)(Woh + soff + 2) = hh;
            *(__nv_bfloat162*)(Wol + soff + 2) = ll;
            if (s == SCH) *(float4*)(g_W0 + soff) = av;
        }
    }
}

// --------------------------------------------------------------------------
// Carry chain: C[k] = W_end[k-1] + Q^32 @ C[k-1].
__global__ void k_carry(int k)
{
    int warp = threadIdx.x >> 5;
    int lane = threadIdx.x & 31;
    const float* cprev = g_Cst + (size_t)(k - 1) * 8192;
    const float* wrow  = g_W0 + (size_t)(k - 1) * 8192;
#pragma unroll
    for (int r = 0; r < 2; r++) {
        int e = blockIdx.x * 16 + warp * 2 + r;
        const float* qrow = g_QS + (size_t)e * 1024;
#pragma unroll
        for (int b = 0; b < 8; b++) {
            float acc = 0.f;
            const float* cp = cprev + b * 1024;
#pragma unroll 4
            for (int d = lane; d < 1024; d += 32) acc += qrow[d] * cp[d];
#pragma unroll
            for (int o = 16; o > 0; o >>= 1) acc += __shfl_xor_sync(0xffffffffu, acc, o);
            if (lane == 0)
                g_Cst[(size_t)k * 8192 + b * 1024 + e] = wrow[b * 1024 + e] + acc;
        }
    }
}

// --------------------------------------------------------------------------
// Pass 2 step s: y_{32k+s} = u + Q y_{32k+s-1}, fp32 in-place in out,
// bf16 hi/lo state double-buffered (s=1 reads seed buffer 1).
__global__ void __launch_bounds__(128)
k_pass2(float* __restrict__ y, int s)
{
    const int rb = s & 1, wb = rb ^ 1;
    const __nv_bfloat16* Yih = g_Ysh[rb];
    const __nv_bfloat16* Yil = g_Ysl[rb];
    __nv_bfloat16* Yoh = g_Ysh[wb];
    __nv_bfloat16* Yol = g_Ysl[wb];

    __shared__ __align__(16) __nv_bfloat16 Ah[64][40];
    __shared__ __align__(16) __nv_bfloat16 Al[64][40];
    __shared__ __align__(16) __nv_bfloat16 Bh[64][40];
    __shared__ __align__(16) __nv_bfloat16 Bl[64][40];
    __shared__ __align__(16) float Cs[64][68];

    const int tid  = threadIdx.x;
    const int warp = tid >> 5;
    const int wr   = warp >> 1, wc = warp & 1;
    const int row0 = blockIdx.y * 64, col0 = blockIdx.x * 64;

    bfc_t acc[2][2];
#pragma unroll
    for (int i = 0; i < 2; i++)
#pragma unroll
        for (int j = 0; j < 2; j++) wmma::fill_fragment(acc[i][j], 0.f);

    for (int k0 = 0; k0 < 1024; k0 += 32) {
#pragma unroll
        for (int l = 0; l < 2; l++) {
            int id = tid + l * 128;
            int r = id >> 2, f = (id & 3) * 8;
            size_t offa = (size_t)(row0 + r) * 1024 + k0 + f;
            *(float4*)&Ah[r][f] = *(const float4*)(Yih + offa);
            *(float4*)&Al[r][f] = *(const float4*)(Yil + offa);
            size_t offb = (size_t)(col0 + r) * 1024 + k0 + f;
            *(float4*)&Bh[r][f] = *(const float4*)(g_Qh + offb);
            *(float4*)&Bl[r][f] = *(const float4*)(g_Ql + offb);
        }
        __syncthreads();
#pragma unroll
        for (int kk = 0; kk < 2; kk++) {
            bfa_t ah[2], al[2];
            bfbc_t bh[2], bl[2];
#pragma unroll
            for (int i = 0; i < 2; i++) {
                wmma::load_matrix_sync(ah[i], &Ah[wr * 32 + i * 16][kk * 16], 40);
                wmma::load_matrix_sync(al[i], &Al[wr * 32 + i * 16][kk * 16], 40);
            }
#pragma unroll
            for (int j = 0; j < 2; j++) {
                wmma::load_matrix_sync(bh[j], &Bh[wc * 32 + j * 16][kk * 16], 40);
                wmma::load_matrix_sync(bl[j], &Bl[wc * 32 + j * 16][kk * 16], 40);
            }
#pragma unroll
            for (int i = 0; i < 2; i++)
#pragma unroll
                for (int j = 0; j < 2; j++) {
                    wmma::mma_sync(acc[i][j], ah[i], bh[j], acc[i][j]);
                    wmma::mma_sync(acc[i][j], al[i], bh[j], acc[i][j]);
                    wmma::mma_sync(acc[i][j], ah[i], bl[j], acc[i][j]);
                }
        }
        __syncthreads();
    }
#pragma unroll
    for (int i = 0; i < 2; i++)
#pragma unroll
        for (int j = 0; j < 2; j++)
            wmma::store_matrix_sync(&Cs[wr * 32 + i * 16][wc * 32 + j * 16],
                                    acc[i][j], 68, wmma::mem_row_major);
    __syncthreads();
#pragma unroll
    for (int l = 0; l < 8; l++) {
        int id = tid + l * 128;
        int r = id >> 4, c4 = (id & 15) * 4;
        int rg = row0 + r;
        int ch = rg >> 3, b = rg & 7;
        int t = ch * SCH + s;
        if (t < LSEQ) {
            int col = col0 + c4;
            float* yp = y + ((size_t)(b * 2048 + t)) * 1024 + col;
            float4 yv = *(float4*)yp;
            float4 av = *(float4*)&Cs[r][c4];
            yv.x += av.x; yv.y += av.y; yv.z += av.z; yv.w += av.w;
            *(float4*)yp = yv;
            size_t soff = (size_t)rg * 1024 + col;
            __nv_bfloat162 hh, ll;
            __nv_bfloat16 h, lo;
            bsplit(yv.x, h, lo); hh.x = h; ll.x = lo;
            bsplit(yv.y, h, lo); hh.y = h; ll.y = lo;
            *(__nv_bfloat162*)(Yoh + soff)     = hh;
            *(__nv_bfloat162*)(Yol + soff)     = ll;
            bsplit(yv.z, h, lo); hh.x = h; ll.x = lo;
            bsplit(yv.w, h, lo); hh.y = h; ll.y = lo;
            *(__nv_bfloat162*)(Yoh + soff + 2) = hh;
            *(__nv_bfloat162*)(Yol + soff + 2) = ll;
        }
    }
}

// --------------------------------------------------------------------------
extern "C" void kernel_launch(void* const* d_in, const int* in_sizes, int n_in,
                              void* d_out, int out_size)
{
    const float* x    = (const float*)d_in[0];
    const float* A_w  = (const float*)d_in[1];
    const float* C_w  = (const float*)d_in[2];
    const float* rc_w = (const float*)d_in[3];
    const float* rc_b = (const float*)d_in[4];
    float* out = (float*)d_out;

    dim3 gsq(16, 16);       // 1024x1024 NN: 16x16 tiles of 64x64
    dim3 gps(16, 8);        // pass kernels: 16 col-tiles x 8 row-tiles

    k_prep_wy<<<4096, 256>>>(rc_w);
    k_split_x<<<65536, 256>>>(x);
    // M = C_w @ A_w
    k_nn<<<gsq, 128>>>(C_w, A_w, -1, -1, BUF_M, 1024);
    // P = M @ Wx (Wx = rc_w[:, :1024], ldb = 3072)
    k_nn<<<gsq, 128>>>(0, rc_w, BUF_M, -1, BUF_P, 3072);
    k_split<<<4096, 256>>>(0);
    // Q = M @ Wy
    k_nn<<<gsq, 128>>>(0, 0, BUF_M, BUF_WY, BUF_Q, 1024);
    k_split<<<4096, 256>>>(1);
    // c = M @ rc_b
    k_matvec_c<<<128, 256>>>(rc_b);
    // U into d_out (t = 1..2047)
    k_nt_u<<<dim3(8, 256), 256>>>(out);
    // Q^32 via 5 squarings
    k_nn<<<gsq, 128>>>(0, 0, BUF_Q,  BUF_Q,  BUF_T1, 1024);
    k_nn<<<gsq, 128>>>(0, 0, BUF_T1, BUF_T1, BUF_T2, 1024);
    k_nn<<<gsq, 128>>>(0, 0, BUF_T2, BUF_T2, BUF_T1, 1024);
    k_nn<<<gsq, 128>>>(0, 0, BUF_T1, BUF_T1, BUF_T2, 1024);
    k_nn<<<gsq, 128>>>(0, 0, BUF_T2, BUF_T2, BUF_QS, 1024);
    // y_0 / C[0]
    k_init<<<32, 256>>>(x, out);
    // pass 1
    for (int s = 1; s <= SCH; s++)
        k_pass1<<<gps, 128>>>(out, s);
    // carry chain
    for (int k = 1; k < NCH; k++)
        k_carry<<<64, 256>>>(k);
    // seed pass-2 state from carries
    k_seed<<<2048, 256>>>();
    // pass 2
    for (int s = 1; s <= SCH; s++)
        k_pass2<<<gps, 128>>>(out, s);
}

// round 11
// speedup vs baseline: 2.2605x; 1.4264x over previous
#include <cuda_runtime.h>
#include <cuda_bf16.h>
#include <mma.h>
#include <cstddef>

using namespace nvcuda;

// ---------------------------------------------------------------------------
// S4Layer: B=8, L=2048, D=1024. Chunked scan: 64 chunks of S=32.
// GEMMs: bf16 tensor MMA m16n16k16, 2-term split (hi*hi + lo*hi + hi*lo).
// Carry chain replaced by 6-round Kogge-Stone matrix scan (GEMM-shaped).
// ---------------------------------------------------------------------------

#define DM 1024
#define NB 8
#define LSEQ 2048
#define SCH 32
#define NCH 64
#define R1 504                     // pass-1 rows = 63 chunks * 8 batch
#define R2 512                     // pass-2 rows = 64 chunks * 8 batch
#define NROW_U (NB * (LSEQ - 1))   // 16376

__device__ float g_M [DM * DM];
__device__ float g_P [DM * DM];
__device__ float g_Q [DM * DM];
__device__ float g_Wy[DM * DM];
__device__ float g_T1[DM * DM];
__device__ float g_T2[DM * DM];
__device__ float g_QS[DM * DM];
__device__ float g_cvec[DM];
__device__ float g_V0[R2 * DM];    // carry-scan state (fp32), double-buffered
__device__ float g_V1[R2 * DM];

// pre-split bf16 hi/lo operands and states
__device__ __nv_bfloat16 g_Ph[DM * DM],  g_Pl[DM * DM];
__device__ __nv_bfloat16 g_Qh[DM * DM],  g_Ql[DM * DM];
__device__ __nv_bfloat16 g_Xh[NB * LSEQ * DM], g_Xl[NB * LSEQ * DM];
__device__ __nv_bfloat16 g_Wsh[2][R1 * DM], g_Wsl[2][R1 * DM];  // pass1 state
__device__ __nv_bfloat16 g_Ysh[2][R2 * DM], g_Ysl[2][R2 * DM];  // pass2 state

#define BUF_M  0
#define BUF_P  1
#define BUF_Q  2
#define BUF_WY 3
#define BUF_T1 4
#define BUF_T2 5
#define BUF_QS 6

__device__ __forceinline__ float* sel_buf(int i)
{
    switch (i) {
        case BUF_M:  return g_M;
        case BUF_P:  return g_P;
        case BUF_Q:  return g_Q;
        case BUF_WY: return g_Wy;
        case BUF_T1: return g_T1;
        case BUF_T2: return g_T2;
        default:     return g_QS;
    }
}

typedef wmma::fragment<wmma::matrix_a, 16, 16, 16, __nv_bfloat16, wmma::row_major> bfa_t;
typedef wmma::fragment<wmma::matrix_b, 16, 16, 16, __nv_bfloat16, wmma::col_major> bfbc_t;
typedef wmma::fragment<wmma::matrix_b, 16, 16, 16, __nv_bfloat16, wmma::row_major> bfbr_t;
typedef wmma::fragment<wmma::accumulator, 16, 16, 16, float> bfc_t;

__device__ __forceinline__ void bsplit(float v, __nv_bfloat16& h, __nv_bfloat16& l)
{
    __nv_bfloat16 hb = __float2bfloat16(v);
    h = hb;
    l = __float2bfloat16(v - __bfloat162float(hb));
}

// --------------------------------------------------------------------------
__global__ void k_prep_wy(const float* __restrict__ rc_w)
{
    int idx = blockIdx.x * blockDim.x + threadIdx.x;   // 1M
    int k = idx >> 10, d = idx & 1023;
    g_Wy[idx] = rc_w[k * 3072 + 1024 + d] + rc_w[k * 3072 + 2048 + d];
}

__global__ void k_split(int which)
{
    int idx = blockIdx.x * blockDim.x + threadIdx.x;   // 1M
    float v = which ? g_Q[idx] : g_P[idx];
    if (which) bsplit(v, g_Qh[idx], g_Ql[idx]);
    else       bsplit(v, g_Ph[idx], g_Pl[idx]);
}

__global__ void k_split_x(const float* __restrict__ x)
{
    int idx = blockIdx.x * blockDim.x + threadIdx.x;   // 16.7M
    bsplit(x[idx], g_Xh[idx], g_Xl[idx]);
}

// Split scanned carries (g_V0) into pass-2 seed state (buffer 1, read by s=1).
__global__ void k_seed()
{
    int idx = blockIdx.x * blockDim.x + threadIdx.x;   // 524288
    bsplit(g_V0[idx], g_Ysh[1][idx], g_Ysl[1][idx]);
}

// --------------------------------------------------------------------------
// NN GEMM (bf16 tensor): C[1024,1024] = A @ B (row-major, B ld = ldb).
// CTA 64x64, 128 threads (4 warps 2x2); fp32 in, split at staging.
__global__ void __launch_bounds__(128)
k_nn(const float* extA, const float* extB, int ia, int ib, int ic, int ldb)
{
    const float* A  = (ia >= 0) ? sel_buf(ia) : extA;
    const float* Bm = (ib >= 0) ? sel_buf(ib) : extB;
    float*       Cm = sel_buf(ic);

    __shared__ __align__(16) __nv_bfloat16 Ah[64][40];
    __shared__ __align__(16) __nv_bfloat16 Al[64][40];
    __shared__ __align__(16) __nv_bfloat16 Bh[32][72];
    __shared__ __align__(16) __nv_bfloat16 Bl[32][72];

    const int tid  = threadIdx.x;
    const int warp = tid >> 5;
    const int wr   = warp >> 1, wc = warp & 1;
    const int row0 = blockIdx.y * 64, col0 = blockIdx.x * 64;

    bfc_t acc[2][2];
#pragma unroll
    for (int i = 0; i < 2; i++)
#pragma unroll
        for (int j = 0; j < 2; j++) wmma::fill_fragment(acc[i][j], 0.f);

    for (int k0 = 0; k0 < 1024; k0 += 32) {
#pragma unroll
        for (int l = 0; l < 4; l++) {
            int id = tid + l * 128;
            int r = id >> 3, c4 = (id & 7) * 4;
            float4 v = *(const float4*)(A + (size_t)(row0 + r) * 1024 + k0 + c4);
            bsplit(v.x, Ah[r][c4 + 0], Al[r][c4 + 0]);
            bsplit(v.y, Ah[r][c4 + 1], Al[r][c4 + 1]);
            bsplit(v.z, Ah[r][c4 + 2], Al[r][c4 + 2]);
            bsplit(v.w, Ah[r][c4 + 3], Al[r][c4 + 3]);
        }
#pragma unroll
        for (int l = 0; l < 4; l++) {
            int id = tid + l * 128;
            int k = id >> 4, n4 = (id & 15) * 4;
            float4 v = *(const float4*)(Bm + (size_t)(k0 + k) * ldb + col0 + n4);
            bsplit(v.x, Bh[k][n4 + 0], Bl[k][n4 + 0]);
            bsplit(v.y, Bh[k][n4 + 1], Bl[k][n4 + 1]);
            bsplit(v.z, Bh[k][n4 + 2], Bl[k][n4 + 2]);
            bsplit(v.w, Bh[k][n4 + 3], Bl[k][n4 + 3]);
        }
        __syncthreads();
#pragma unroll
        for (int kk = 0; kk < 2; kk++) {
            bfa_t ah[2], al[2];
            bfbr_t bh[2], bl[2];
#pragma unroll
            for (int i = 0; i < 2; i++) {
                wmma::load_matrix_sync(ah[i], &Ah[wr * 32 + i * 16][kk * 16], 40);
                wmma::load_matrix_sync(al[i], &Al[wr * 32 + i * 16][kk * 16], 40);
            }
#pragma unroll
            for (int j = 0; j < 2; j++) {
                wmma::load_matrix_sync(bh[j], &Bh[kk * 16][wc * 32 + j * 16], 72);
                wmma::load_matrix_sync(bl[j], &Bl[kk * 16][wc * 32 + j * 16], 72);
            }
#pragma unroll
            for (int i = 0; i < 2; i++)
#pragma unroll
                for (int j = 0; j < 2; j++) {
                    wmma::mma_sync(acc[i][j], ah[i], bh[j], acc[i][j]);
                    wmma::mma_sync(acc[i][j], al[i], bh[j], acc[i][j]);
                    wmma::mma_sync(acc[i][j], ah[i], bl[j], acc[i][j]);
                }
        }
        __syncthreads();
    }
#pragma unroll
    for (int i = 0; i < 2; i++)
#pragma unroll
        for (int j = 0; j < 2; j++)
            wmma::store_matrix_sync(
                Cm + (size_t)(row0 + wr * 32 + i * 16) * 1024 + col0 + wc * 32 + j * 16,
                acc[i][j], 1024, wmma::mem_row_major);
}

// --------------------------------------------------------------------------
// Kogge-Stone carry-scan round: Bnew[r] = Bold[r] + Bold[r - o8] @ Pm^T
// (rows with r < o8: Bnew = Bold). 512 rows. CTA 64x64, 128 threads.
// dir: 0 = V0->V1, 1 = V1->V0. Pm = sel_buf(ip) = (Q^32)^o.
__global__ void __launch_bounds__(128)
k_scan(int dir, int ip, int o8)
{
    const float* Bold = dir ? g_V1 : g_V0;
    float*       Bnew = dir ? g_V0 : g_V1;
    const float* Pm   = sel_buf(ip);

    __shared__ __align__(16) __nv_bfloat16 Ah[64][40];
    __shared__ __align__(16) __nv_bfloat16 Al[64][40];
    __shared__ __align__(16) __nv_bfloat16 Bh[64][40];
    __shared__ __align__(16) __nv_bfloat16 Bl[64][40];
    __shared__ __align__(16) float Cs[64][68];

    const int tid  = threadIdx.x;
    const int warp = tid >> 5;
    const int wr   = warp >> 1, wc = warp & 1;
    const int row0 = blockIdx.y * 64, col0 = blockIdx.x * 64;

    bfc_t acc[2][2];
#pragma unroll
    for (int i = 0; i < 2; i++)
#pragma unroll
        for (int j = 0; j < 2; j++) wmma::fill_fragment(acc[i][j], 0.f);

    for (int k0 = 0; k0 < 1024; k0 += 32) {
#pragma unroll
        for (int l = 0; l < 4; l++) {          // A: shifted Bold rows, split
            int id = tid + l * 128;
            int r = id >> 3, c4 = (id & 7) * 4;
            int ra = row0 + r - o8;
            float4 v = (ra >= 0)
                ? *(const float4*)(Bold + (size_t)ra * 1024 + k0 + c4)
                : make_float4(0.f, 0.f, 0.f, 0.f);
            bsplit(v.x, Ah[r][c4 + 0], Al[r][c4 + 0]);
            bsplit(v.y, Ah[r][c4 + 1], Al[r][c4 + 1]);
            bsplit(v.z, Ah[r][c4 + 2], Al[r][c4 + 2]);
            bsplit(v.w, Ah[r][c4 + 3], Al[r][c4 + 3]);
        }
#pragma unroll
        for (int l = 0; l < 4; l++) {          // B: Pm rows (output cols), split
            int id = tid + l * 128;
            int r = id >> 3, c4 = (id & 7) * 4;
            float4 v = *(const float4*)(Pm + (size_t)(col0 + r) * 1024 + k0 + c4);
            bsplit(v.x, Bh[r][c4 + 0], Bl[r][c4 + 0]);
            bsplit(v.y, Bh[r][c4 + 1], Bl[r][c4 + 1]);
            bsplit(v.z, Bh[r][c4 + 2], Bl[r][c4 + 2]);
            bsplit(v.w, Bh[r][c4 + 3], Bl[r][c4 + 3]);
        }
        __syncthreads();
#pragma unroll
        for (int kk = 0; kk < 2; kk++) {
            bfa_t ah[2], al[2];
            bfbc_t bh[2], bl[2];
#pragma unroll
            for (int i = 0; i < 2; i++) {
                wmma::load_matrix_sync(ah[i], &Ah[wr * 32 + i * 16][kk * 16], 40);
                wmma::load_matrix_sync(al[i], &Al[wr * 32 + i * 16][kk * 16], 40);
            }
#pragma unroll
            for (int j = 0; j < 2; j++) {
                wmma::load_matrix_sync(bh[j], &Bh[wc * 32 + j * 16][kk * 16], 40);
                wmma::load_matrix_sync(bl[j], &Bl[wc * 32 + j * 16][kk * 16], 40);
            }
#pragma unroll
            for (int i = 0; i < 2; i++)
#pragma unroll
                for (int j = 0; j < 2; j++) {
                    wmma::mma_sync(acc[i][j], ah[i], bh[j], acc[i][j]);
                    wmma::mma_sync(acc[i][j], al[i], bh[j], acc[i][j]);
                    wmma::mma_sync(acc[i][j], ah[i], bl[j], acc[i][j]);
                }
        }
        __syncthreads();
    }
#pragma unroll
    for (int i = 0; i < 2; i++)
#pragma unroll
        for (int j = 0; j < 2; j++)
            wmma::store_matrix_sync(&Cs[wr * 32 + i * 16][wc * 32 + j * 16],
                                    acc[i][j], 68, wmma::mem_row_major);
    __syncthreads();
#pragma unroll
    for (int l = 0; l < 8; l++) {
        int id = tid + l * 128;
        int r = id >> 4, c4 = (id & 15) * 4;
        int rg = row0 + r;
        int col = col0 + c4;
        size_t off = (size_t)rg * 1024 + col;
        float4 bv = *(const float4*)(Bold + off);
        float4 av = *(float4*)&Cs[r][c4];
        av.x += bv.x; av.y += bv.y; av.z += bv.z; av.w += bv.w;
        *(float4*)(Bnew + off) = av;
    }
}

// --------------------------------------------------------------------------
__global__ void k_matvec_c(const float* __restrict__ rc_b)
{
    int e = blockIdx.x * 8 + (threadIdx.x >> 5);
    int lane = threadIdx.x & 31;
    const float* mr = g_M + (size_t)e * 1024;
    float acc = 0.f;
#pragma unroll 4
    for (int d = lane; d < 1024; d += 32) acc += mr[d] * rc_b[d];
#pragma unroll
    for (int o = 16; o > 0; o >>= 1) acc += __shfl_xor_sync(0xffffffffu, acc, o);
    if (lane == 0) g_cvec[e] = acc;
}

// --------------------------------------------------------------------------
// U GEMM (bf16, NT): out[b,t,:] = x[b,t,:] @ P^T + c, t=1..2047.
__global__ void __launch_bounds__(256)
k_nt_u(float* __restrict__ out)
{
    __shared__ __align__(16) char sm[64 * 132 * 4];   // 33792 B union
    __nv_bfloat16 (*Ah)[40] = (__nv_bfloat16(*)[40])(sm);
    __nv_bfloat16 (*Al)[40] = (__nv_bfloat16(*)[40])(sm + 5120);
    __nv_bfloat16 (*Bh)[40] = (__nv_bfloat16(*)[40])(sm + 10240);
    __nv_bfloat16 (*Bl)[40] = (__nv_bfloat16(*)[40])(sm + 20480);
    float (*Cs)[132]        = (float(*)[132])(sm);

    const int tid  = threadIdx.x;
    const int warp = tid >> 5;
    const int wr   = warp >> 2, wc = warp & 3;
    const int row0 = blockIdx.y * 64, col0 = blockIdx.x * 128;

    bfc_t acc[2][2];
#pragma unroll
    for (int i = 0; i < 2; i++)
#pragma unroll
        for (int j = 0; j < 2; j++) wmma::fill_fragment(acc[i][j], 0.f);

    const int ar = tid >> 2, af = (tid & 3) * 8;
    size_t axoff;
    {
        int rg = row0 + ar;
        int b = 0, t = 0;
        if (rg < NROW_U) { b = rg / 2047; t = 1 + rg % 2047; }
        axoff = ((size_t)(b * 2048 + t)) * 1024;
    }

    for (int k0 = 0; k0 < 1024; k0 += 32) {
        *(float4*)&Ah[ar][af] = *(const float4*)(g_Xh + axoff + k0 + af);
        *(float4*)&Al[ar][af] = *(const float4*)(g_Xl + axoff + k0 + af);
#pragma unroll
        for (int l = 0; l < 2; l++) {
            int id = tid + l * 256;
            int n = id >> 2, f = (id & 3) * 8;
            size_t off = (size_t)(col0 + n) * 1024 + k0 + f;
            *(float4*)&Bh[n][f] = *(const float4*)(g_Ph + off);
            *(float4*)&Bl[n][f] = *(const float4*)(g_Pl + off);
        }
        __syncthreads();
#pragma unroll
        for (int kk = 0; kk < 2; kk++) {
            bfa_t ah[2], al[2];
            bfbc_t bh[2], bl[2];
#pragma unroll
            for (int i = 0; i < 2; i++) {
                wmma::load_matrix_sync(ah[i], &Ah[wr * 32 + i * 16][kk * 16], 40);
                wmma::load_matrix_sync(al[i], &Al[wr * 32 + i * 16][kk * 16], 40);
            }
#pragma unroll
            for (int j = 0; j < 2; j++) {
                wmma::load_matrix_sync(bh[j], &Bh[wc * 32 + j * 16][kk * 16], 40);
                wmma::load_matrix_sync(bl[j], &Bl[wc * 32 + j * 16][kk * 16], 40);
            }
#pragma unroll
            for (int i = 0; i < 2; i++)
#pragma unroll
                for (int j = 0; j < 2; j++) {
                    wmma::mma_sync(acc[i][j], ah[i], bh[j], acc[i][j]);
                    wmma::mma_sync(acc[i][j], al[i], bh[j], acc[i][j]);
                    wmma::mma_sync(acc[i][j], ah[i], bl[j], acc[i][j]);
                }
        }
        __syncthreads();
    }
#pragma unroll
    for (int i = 0; i < 2; i++)
#pragma unroll
        for (int j = 0; j < 2; j++)
            wmma::store_matrix_sync(&Cs[wr * 32 + i * 16][wc * 32 + j * 16],
                                    acc[i][j], 132, wmma::mem_row_major);
    __syncthreads();
#pragma unroll
    for (int l = 0; l < 8; l++) {
        int id = tid + l * 256;
        int r = id >> 5, c4 = (id & 31) * 4;
        int rg = row0 + r;
        if (rg < NROW_U) {
            int b = rg / 2047, t = 1 + rg % 2047;
            float4 v = *(float4*)&Cs[r][c4];
            int col = col0 + c4;
            v.x += g_cvec[col + 0]; v.y += g_cvec[col + 1];
            v.z += g_cvec[col + 2]; v.w += g_cvec[col + 3];
            *(float4*)(out + ((size_t)(b * 2048 + t)) * 1024 + col) = v;
        }
    }
}

// --------------------------------------------------------------------------
// out[b,0,:] = x[b,0,:] ; V0 rows 0..7 = y_0
__global__ void k_init(const float* __restrict__ x, float* __restrict__ out)
{
    int idx = blockIdx.x * blockDim.x + threadIdx.x;   // 8192
    int b = idx >> 10, e = idx & 1023;
    float v = x[((size_t)b * 2048) * 1024 + e];
    out[((size_t)b * 2048) * 1024 + e] = v;
    g_V0[idx] = v;                 // row b (= chunk 0), col e
}

// --------------------------------------------------------------------------
// Pass 1 step s: w <- Q @ w + u_{32k+s}, chunks 0..62 (504 rows).
// CTA 64x64, 128 threads. State in bf16 hi/lo, double-buffered.
// At s==SCH, writes fp32 chunk-end sums into g_V0 rows (ch+1)*8+b.
__global__ void __launch_bounds__(128)
k_pass1(const float* __restrict__ u, int s)
{
    const int wb = s & 1, rb = wb ^ 1;
    const __nv_bfloat16* Wih = g_Wsh[rb];
    const __nv_bfloat16* Wil = g_Wsl[rb];
    __nv_bfloat16* Woh = g_Wsh[wb];
    __nv_bfloat16* Wol = g_Wsl[wb];

    __shared__ __align__(16) __nv_bfloat16 Ah[64][40];
    __shared__ __align__(16) __nv_bfloat16 Al[64][40];
    __shared__ __align__(16) __nv_bfloat16 Bh[64][40];
    __shared__ __align__(16) __nv_bfloat16 Bl[64][40];
    __shared__ __align__(16) float Cs[64][68];

    const int tid  = threadIdx.x;
    const int warp = tid >> 5;
    const int wr   = warp >> 1, wc = warp & 1;
    const int row0 = blockIdx.y * 64, col0 = blockIdx.x * 64;

    bfc_t acc[2][2];
#pragma unroll
    for (int i = 0; i < 2; i++)
#pragma unroll
        for (int j = 0; j < 2; j++) wmma::fill_fragment(acc[i][j], 0.f);

    if (s > 1) {
        for (int k0 = 0; k0 < 1024; k0 += 32) {
#pragma unroll
            for (int l = 0; l < 2; l++) {
                int id = tid + l * 128;
                int r = id >> 2, f = (id & 3) * 8;
                int rg = row0 + r;
                int rga = (rg < R1) ? rg : 0;
                size_t offa = (size_t)rga * 1024 + k0 + f;
                *(float4*)&Ah[r][f] = *(const float4*)(Wih + offa);
                *(float4*)&Al[r][f] = *(const float4*)(Wil + offa);
                size_t offb = (size_t)(col0 + r) * 1024 + k0 + f;
                *(float4*)&Bh[r][f] = *(const float4*)(g_Qh + offb);
                *(float4*)&Bl[r][f] = *(const float4*)(g_Ql + offb);
            }
            __syncthreads();
#pragma unroll
            for (int kk = 0; kk < 2; kk++) {
                bfa_t ah[2], al[2];
                bfbc_t bh[2], bl[2];
#pragma unroll
                for (int i = 0; i < 2; i++) {
                    wmma::load_matrix_sync(ah[i], &Ah[wr * 32 + i * 16][kk * 16], 40);
                    wmma::load_matrix_sync(al[i], &Al[wr * 32 + i * 16][kk * 16], 40);
                }
#pragma unroll
                for (int j = 0; j < 2; j++) {
                    wmma::load_matrix_sync(bh[j], &Bh[wc * 32 + j * 16][kk * 16], 40);
                    wmma::load_matrix_sync(bl[j], &Bl[wc * 32 + j * 16][kk * 16], 40);
                }
#pragma unroll
                for (int i = 0; i < 2; i++)
#pragma unroll
                    for (int j = 0; j < 2; j++) {
                        wmma::mma_sync(acc[i][j], ah[i], bh[j], acc[i][j]);
                        wmma::mma_sync(acc[i][j], al[i], bh[j], acc[i][j]);
                        wmma::mma_sync(acc[i][j], ah[i], bl[j], acc[i][j]);
                    }
            }
            __syncthreads();
        }
    }
#pragma unroll
    for (int i = 0; i < 2; i++)
#pragma unroll
        for (int j = 0; j < 2; j++)
            wmma::store_matrix_sync(&Cs[wr * 32 + i * 16][wc * 32 + j * 16],
                                    acc[i][j], 68, wmma::mem_row_major);
    __syncthreads();
#pragma unroll
    for (int l = 0; l < 8; l++) {
        int id = tid + l * 128;
        int r = id >> 4, c4 = (id & 15) * 4;
        int rg = row0 + r;
        if (rg < R1) {
            int ch = rg >> 3, b = rg & 7;
            int t = ch * SCH + s;
            int col = col0 + c4;
            float4 uv = *(const float4*)(u + ((size_t)(b * 2048 + t)) * 1024 + col);
            float4 av = *(float4*)&Cs[r][c4];
            av.x += uv.x; av.y += uv.y; av.z += uv.z; av.w += uv.w;
            size_t soff = (size_t)rg * 1024 + col;
            __nv_bfloat162 hh, ll;
            __nv_bfloat16 h, lo;
            bsplit(av.x, h, lo); hh.x = h; ll.x = lo;
            bsplit(av.y, h, lo); hh.y = h; ll.y = lo;
            *(__nv_bfloat162*)(Woh + soff)     = hh;
            *(__nv_bfloat162*)(Wol + soff)     = ll;
            bsplit(av.z, h, lo); hh.x = h; ll.x = lo;
            bsplit(av.w, h, lo); hh.y = h; ll.y = lo;
            *(__nv_bfloat162*)(Woh + soff + 2) = hh;
            *(__nv_bfloat162*)(Wol + soff + 2) = ll;
            if (s == SCH)
                *(float4*)(g_V0 + (size_t)(rg + 8) * 1024 + col) = av;
        }
    }
}

// --------------------------------------------------------------------------
// Pass 2 step s: y_{32k+s} = u + Q y_{32k+s-1}, fp32 in-place in out,
// bf16 hi/lo state double-buffered (s=1 reads seed buffer 1).
__global__ void __launch_bounds__(128)
k_pass2(float* __restrict__ y, int s)
{
    const int rb = s & 1, wb = rb ^ 1;
    const __nv_bfloat16* Yih = g_Ysh[rb];
    const __nv_bfloat16* Yil = g_Ysl[rb];
    __nv_bfloat16* Yoh = g_Ysh[wb];
    __nv_bfloat16* Yol = g_Ysl[wb];

    __shared__ __align__(16) __nv_bfloat16 Ah[64][40];
    __shared__ __align__(16) __nv_bfloat16 Al[64][40];
    __shared__ __align__(16) __nv_bfloat16 Bh[64][40];
    __shared__ __align__(16) __nv_bfloat16 Bl[64][40];
    __shared__ __align__(16) float Cs[64][68];

    const int tid  = threadIdx.x;
    const int warp = tid >> 5;
    const int wr   = warp >> 1, wc = warp & 1;
    const int row0 = blockIdx.y * 64, col0 = blockIdx.x * 64;

    bfc_t acc[2][2];
#pragma unroll
    for (int i = 0; i < 2; i++)
#pragma unroll
        for (int j = 0; j < 2; j++) wmma::fill_fragment(acc[i][j], 0.f);

    for (int k0 = 0; k0 < 1024; k0 += 32) {
#pragma unroll
        for (int l = 0; l < 2; l++) {
            int id = tid + l * 128;
            int r = id >> 2, f = (id & 3) * 8;
            size_t offa = (size_t)(row0 + r) * 1024 + k0 + f;
            *(float4*)&Ah[r][f] = *(const float4*)(Yih + offa);
            *(float4*)&Al[r][f] = *(const float4*)(Yil + offa);
            size_t offb = (size_t)(col0 + r) * 1024 + k0 + f;
            *(float4*)&Bh[r][f] = *(const float4*)(g_Qh + offb);
            *(float4*)&Bl[r][f] = *(const float4*)(g_Ql + offb);
        }
        __syncthreads();
#pragma unroll
        for (int kk = 0; kk < 2; kk++) {
            bfa_t ah[2], al[2];
            bfbc_t bh[2], bl[2];
#pragma unroll
            for (int i = 0; i < 2; i++) {
                wmma::load_matrix_sync(ah[i], &Ah[wr * 32 + i * 16][kk * 16], 40);
                wmma::load_matrix_sync(al[i], &Al[wr * 32 + i * 16][kk * 16], 40);
            }
#pragma unroll
            for (int j = 0; j < 2; j++) {
                wmma::load_matrix_sync(bh[j], &Bh[wc * 32 + j * 16][kk * 16], 40);
                wmma::load_matrix_sync(bl[j], &Bl[wc * 32 + j * 16][kk * 16], 40);
            }
#pragma unroll
            for (int i = 0; i < 2; i++)
#pragma unroll
                for (int j = 0; j < 2; j++) {
                    wmma::mma_sync(acc[i][j], ah[i], bh[j], acc[i][j]);
                    wmma::mma_sync(acc[i][j], al[i], bh[j], acc[i][j]);
                    wmma::mma_sync(acc[i][j], ah[i], bl[j], acc[i][j]);
                }
        }
        __syncthreads();
    }
#pragma unroll
    for (int i = 0; i < 2; i++)
#pragma unroll
        for (int j = 0; j < 2; j++)
            wmma::store_matrix_sync(&Cs[wr * 32 + i * 16][wc * 32 + j * 16],
                                    acc[i][j], 68, wmma::mem_row_major);
    __syncthreads();
#pragma unroll
    for (int l = 0; l < 8; l++) {
        int id = tid + l * 128;
        int r = id >> 4, c4 = (id & 15) * 4;
        int rg = row0 + r;
        int ch = rg >> 3, b = rg & 7;
        int t = ch * SCH + s;
        if (t < LSEQ) {
            int col = col0 + c4;
            float* yp = y + ((size_t)(b * 2048 + t)) * 1024 + col;
            float4 yv = *(float4*)yp;
            float4 av = *(float4*)&Cs[r][c4];
            yv.x += av.x; yv.y += av.y; yv.z += av.z; yv.w += av.w;
            *(float4*)yp = yv;
            size_t soff = (size_t)rg * 1024 + col;
            __nv_bfloat162 hh, ll;
            __nv_bfloat16 h, lo;
            bsplit(yv.x, h, lo); hh.x = h; ll.x = lo;
            bsplit(yv.y, h, lo); hh.y = h; ll.y = lo;
            *(__nv_bfloat162*)(Yoh + soff)     = hh;
            *(__nv_bfloat162*)(Yol + soff)     = ll;
            bsplit(yv.z, h, lo); hh.x = h; ll.x = lo;
            bsplit(yv.w, h, lo); hh.y = h; ll.y = lo;
            *(__nv_bfloat162*)(Yoh + soff + 2) = hh;
            *(__nv_bfloat162*)(Yol + soff + 2) = ll;
        }
    }
}

// --------------------------------------------------------------------------
extern "C" void kernel_launch(void* const* d_in, const int* in_sizes, int n_in,
                              void* d_out, int out_size)
{
    const float* x    = (const float*)d_in[0];
    const float* A_w  = (const float*)d_in[1];
    const float* C_w  = (const float*)d_in[2];
    const float* rc_w = (const float*)d_in[3];
    const float* rc_b = (const float*)d_in[4];
    float* out = (float*)d_out;

    dim3 gsq(16, 16);       // 1024x1024 NN: 16x16 tiles of 64x64
    dim3 gps(16, 8);        // pass/scan kernels: 16 col-tiles x 8 row-tiles

    k_prep_wy<<<4096, 256>>>(rc_w);
    k_split_x<<<65536, 256>>>(x);
    // M = C_w @ A_w
    k_nn<<<gsq, 128>>>(C_w, A_w, -1, -1, BUF_M, 1024);
    // P = M @ Wx (Wx = rc_w[:, :1024], ldb = 3072)
    k_nn<<<gsq, 128>>>(0, rc_w, BUF_M, -1, BUF_P, 3072);
    k_split<<<4096, 256>>>(0);
    // Q = M @ Wy
    k_nn<<<gsq, 128>>>(0, 0, BUF_M, BUF_WY, BUF_Q, 1024);
    k_split<<<4096, 256>>>(1);
    // c = M @ rc_b
    k_matvec_c<<<128, 256>>>(rc_b);
    // U into d_out (t = 1..2047)
    k_nt_u<<<dim3(8, 256), 256>>>(out);
    // Q^32 via 5 squarings
    k_nn<<<gsq, 128>>>(0, 0, BUF_Q,  BUF_Q,  BUF_T1, 1024);
    k_nn<<<gsq, 128>>>(0, 0, BUF_T1, BUF_T1, BUF_T2, 1024);
    k_nn<<<gsq, 128>>>(0, 0, BUF_T2, BUF_T2, BUF_T1, 1024);
    k_nn<<<gsq, 128>>>(0, 0, BUF_T1, BUF_T1, BUF_T2, 1024);
    k_nn<<<gsq, 128>>>(0, 0, BUF_T2, BUF_T2, BUF_QS, 1024);
    // y_0 -> out and V0 rows 0..7
    k_init<<<32, 256>>>(x, out);
    // pass 1 (s==32 deposits chunk-end sums into V0 rows 8..511)
    for (int s = 1; s <= SCH; s++)
        k_pass1<<<gps, 128>>>(out, s);
    // Kogge-Stone carry scan: offsets 1,2,4,8,16,32 (powers of Q^32)
    k_scan<<<gps, 128>>>(0, BUF_QS, 8);                       // V0->V1, o=1
    k_nn<<<gsq, 128>>>(0, 0, BUF_QS, BUF_QS, BUF_T1, 1024);   // T1 = Q^64
    k_scan<<<gps, 128>>>(1, BUF_T1, 16);                      // V1->V0, o=2
    k_nn<<<gsq, 128>>>(0, 0, BUF_T1, BUF_T1, BUF_T2, 1024);   // T2 = Q^128
    k_scan<<<gps, 128>>>(0, BUF_T2, 32);                      // V0->V1, o=4
    k_nn<<<gsq, 128>>>(0, 0, BUF_T2, BUF_T2, BUF_T1, 1024);   // T1 = Q^256
    k_scan<<<gps, 128>>>(1, BUF_T1, 64);                      // V1->V0, o=8
    k_nn<<<gsq, 128>>>(0, 0, BUF_T1, BUF_T1, BUF_T2, 1024);   // T2 = Q^512
    k_scan<<<gps, 128>>>(0, BUF_T2, 128);                     // V0->V1, o=16
    k_nn<<<gsq, 128>>>(0, 0, BUF_T2, BUF_T2, BUF_T1, 1024);   // T1 = Q^1024
    k_scan<<<gps, 128>>>(1, BUF_T1, 256);                     // V1->V0, o=32
    // seed pass-2 state from scanned carries (V0)
    k_seed<<<2048, 256>>>();
    // pass 2
    for (int s = 1; s <= SCH; s++)
        k_pass2<<<gps, 128>>>(out, s);
}

// round 13
// speedup vs baseline: 2.9278x; 1.2952x over previous
#include <cuda_runtime.h>
#include <cuda_bf16.h>
#include <mma.h>
#include <cstddef>
#include <cstdint>

using namespace nvcuda;

// ---------------------------------------------------------------------------
// S4Layer: B=8, L=2048, D=1024. Chunked scan: 64 chunks of S=32.
// GEMMs: bf16 tensor MMA m16n16k16, 2-term split (hi*hi + lo*hi + hi*lo).
// Carry chain: 6-round Kogge-Stone matrix scan (GEMM-shaped).
// Hot kernels (pass1/pass2/nt_u): cp.async double-buffered smem pipeline.
// ---------------------------------------------------------------------------

#define DM 1024
#define NB 8
#define LSEQ 2048
#define SCH 32
#define NCH 64
#define R1 504                     // pass-1 rows = 63 chunks * 8 batch
#define R2 512                     // pass-2 rows = 64 chunks * 8 batch
#define NROW_U (NB * (LSEQ - 1))   // 16376

__device__ float g_M [DM * DM];
__device__ float g_P [DM * DM];
__device__ float g_Q [DM * DM];
__device__ float g_Wy[DM * DM];
__device__ float g_T1[DM * DM];
__device__ float g_T2[DM * DM];
__device__ float g_QS[DM * DM];
__device__ float g_cvec[DM];
__device__ float g_V0[R2 * DM];    // carry-scan state (fp32), double-buffered
__device__ float g_V1[R2 * DM];

// pre-split bf16 hi/lo operands and states
__device__ __nv_bfloat16 g_Ph[DM * DM],  g_Pl[DM * DM];
__device__ __nv_bfloat16 g_Qh[DM * DM],  g_Ql[DM * DM];
__device__ __nv_bfloat16 g_Xh[NB * LSEQ * DM], g_Xl[NB * LSEQ * DM];
__device__ __nv_bfloat16 g_Wsh[2][R1 * DM], g_Wsl[2][R1 * DM];  // pass1 state
__device__ __nv_bfloat16 g_Ysh[2][R2 * DM], g_Ysl[2][R2 * DM];  // pass2 state

#define BUF_M  0
#define BUF_P  1
#define BUF_Q  2
#define BUF_WY 3
#define BUF_T1 4
#define BUF_T2 5
#define BUF_QS 6

__device__ __forceinline__ float* sel_buf(int i)
{
    switch (i) {
        case BUF_M:  return g_M;
        case BUF_P:  return g_P;
        case BUF_Q:  return g_Q;
        case BUF_WY: return g_Wy;
        case BUF_T1: return g_T1;
        case BUF_T2: return g_T2;
        default:     return g_QS;
    }
}

typedef wmma::fragment<wmma::matrix_a, 16, 16, 16, __nv_bfloat16, wmma::row_major> bfa_t;
typedef wmma::fragment<wmma::matrix_b, 16, 16, 16, __nv_bfloat16, wmma::col_major> bfbc_t;
typedef wmma::fragment<wmma::matrix_b, 16, 16, 16, __nv_bfloat16, wmma::row_major> bfbr_t;
typedef wmma::fragment<wmma::accumulator, 16, 16, 16, float> bfc_t;

__device__ __forceinline__ void bsplit(float v, __nv_bfloat16& h, __nv_bfloat16& l)
{
    __nv_bfloat16 hb = __float2bfloat16(v);
    h = hb;
    l = __float2bfloat16(v - __bfloat162float(hb));
}

__device__ __forceinline__ uint32_t s2u(const void* p)
{
    uint32_t a;
    asm("{ .reg .u64 t; cvta.to.shared.u64 t, %1; cvt.u32.u64 %0, t; }"
        : "=r"(a) : "l"(p));
    return a;
}
#define CPA16(s, g)   asm volatile("cp.async.ca.shared.global [%0], [%1], 16;" :: "r"(s), "l"(g))
#define CPA_COMMIT()  asm volatile("cp.async.commit_group;" ::: "memory")
#define CPA_WAIT(n)   asm volatile("cp.async.wait_group %0;" :: "n"(n) : "memory")

// per-buffer smem layout for the pipelined 64x64 kernels (bytes):
//   Ah @ 0, Al @ 5120, Bh @ 10240, Bl @ 15360  (each 64 x 40 bf16 = 5120 B)
#define PBUF 20480

// --------------------------------------------------------------------------
__global__ void k_prep_wy(const float* __restrict__ rc_w)
{
    int idx = blockIdx.x * blockDim.x + threadIdx.x;   // 1M
    int k = idx >> 10, d = idx & 1023;
    g_Wy[idx] = rc_w[k * 3072 + 1024 + d] + rc_w[k * 3072 + 2048 + d];
}

__global__ void k_split(int which)
{
    int idx = blockIdx.x * blockDim.x + threadIdx.x;   // 1M
    float v = which ? g_Q[idx] : g_P[idx];
    if (which) bsplit(v, g_Qh[idx], g_Ql[idx]);
    else       bsplit(v, g_Ph[idx], g_Pl[idx]);
}

__global__ void k_split_x(const float* __restrict__ x)
{
    int idx = blockIdx.x * blockDim.x + threadIdx.x;   // 16.7M
    bsplit(x[idx], g_Xh[idx], g_Xl[idx]);
}

__global__ void k_seed()
{
    int idx = blockIdx.x * blockDim.x + threadIdx.x;   // 524288
    bsplit(g_V0[idx], g_Ysh[1][idx], g_Ysl[1][idx]);
}

// --------------------------------------------------------------------------
// NN GEMM (bf16 tensor): C[1024,1024] = A @ B (row-major, B ld = ldb).
// CTA 64x64, 128 threads; fp32 in, split at staging (cold path, unpipelined).
__global__ void __launch_bounds__(128)
k_nn(const float* extA, const float* extB, int ia, int ib, int ic, int ldb)
{
    const float* A  = (ia >= 0) ? sel_buf(ia) : extA;
    const float* Bm = (ib >= 0) ? sel_buf(ib) : extB;
    float*       Cm = sel_buf(ic);

    __shared__ __align__(16) __nv_bfloat16 Ah[64][40];
    __shared__ __align__(16) __nv_bfloat16 Al[64][40];
    __shared__ __align__(16) __nv_bfloat16 Bh[32][72];
    __shared__ __align__(16) __nv_bfloat16 Bl[32][72];

    const int tid  = threadIdx.x;
    const int warp = tid >> 5;
    const int wr   = warp >> 1, wc = warp & 1;
    const int row0 = blockIdx.y * 64, col0 = blockIdx.x * 64;

    bfc_t acc[2][2];
#pragma unroll
    for (int i = 0; i < 2; i++)
#pragma unroll
        for (int j = 0; j < 2; j++) wmma::fill_fragment(acc[i][j], 0.f);

    for (int k0 = 0; k0 < 1024; k0 += 32) {
#pragma unroll
        for (int l = 0; l < 4; l++) {
            int id = tid + l * 128;
            int r = id >> 3, c4 = (id & 7) * 4;
            float4 v = *(const float4*)(A + (size_t)(row0 + r) * 1024 + k0 + c4);
            bsplit(v.x, Ah[r][c4 + 0], Al[r][c4 + 0]);
            bsplit(v.y, Ah[r][c4 + 1], Al[r][c4 + 1]);
            bsplit(v.z, Ah[r][c4 + 2], Al[r][c4 + 2]);
            bsplit(v.w, Ah[r][c4 + 3], Al[r][c4 + 3]);
        }
#pragma unroll
        for (int l = 0; l < 4; l++) {
            int id = tid + l * 128;
            int k = id >> 4, n4 = (id & 15) * 4;
            float4 v = *(const float4*)(Bm + (size_t)(k0 + k) * ldb + col0 + n4);
            bsplit(v.x, Bh[k][n4 + 0], Bl[k][n4 + 0]);
            bsplit(v.y, Bh[k][n4 + 1], Bl[k][n4 + 1]);
            bsplit(v.z, Bh[k][n4 + 2], Bl[k][n4 + 2]);
            bsplit(v.w, Bh[k][n4 + 3], Bl[k][n4 + 3]);
        }
        __syncthreads();
#pragma unroll
        for (int kk = 0; kk < 2; kk++) {
            bfa_t ah[2], al[2];
            bfbr_t bh[2], bl[2];
#pragma unroll
            for (int i = 0; i < 2; i++) {
                wmma::load_matrix_sync(ah[i], &Ah[wr * 32 + i * 16][kk * 16], 40);
                wmma::load_matrix_sync(al[i], &Al[wr * 32 + i * 16][kk * 16], 40);
            }
#pragma unroll
            for (int j = 0; j < 2; j++) {
                wmma::load_matrix_sync(bh[j], &Bh[kk * 16][wc * 32 + j * 16], 72);
                wmma::load_matrix_sync(bl[j], &Bl[kk * 16][wc * 32 + j * 16], 72);
            }
#pragma unroll
            for (int i = 0; i < 2; i++)
#pragma unroll
                for (int j = 0; j < 2; j++) {
                    wmma::mma_sync(acc[i][j], ah[i], bh[j], acc[i][j]);
                    wmma::mma_sync(acc[i][j], al[i], bh[j], acc[i][j]);
                    wmma::mma_sync(acc[i][j], ah[i], bl[j], acc[i][j]);
                }
        }
        __syncthreads();
    }
#pragma unroll
    for (int i = 0; i < 2; i++)
#pragma unroll
        for (int j = 0; j < 2; j++)
            wmma::store_matrix_sync(
                Cm + (size_t)(row0 + wr * 32 + i * 16) * 1024 + col0 + wc * 32 + j * 16,
                acc[i][j], 1024, wmma::mem_row_major);
}

// --------------------------------------------------------------------------
// Kogge-Stone carry-scan round (unpipelined, cold): Bnew = Bold + shift @ Pm^T.
__global__ void __launch_bounds__(128)
k_scan(int dir, int ip, int o8)
{
    const float* Bold = dir ? g_V1 : g_V0;
    float*       Bnew = dir ? g_V0 : g_V1;
    const float* Pm   = sel_buf(ip);

    __shared__ __align__(16) __nv_bfloat16 Ah[64][40];
    __shared__ __align__(16) __nv_bfloat16 Al[64][40];
    __shared__ __align__(16) __nv_bfloat16 Bh[64][40];
    __shared__ __align__(16) __nv_bfloat16 Bl[64][40];
    __shared__ __align__(16) float Cs[64][68];

    const int tid  = threadIdx.x;
    const int warp = tid >> 5;
    const int wr   = warp >> 1, wc = warp & 1;
    const int row0 = blockIdx.y * 64, col0 = blockIdx.x * 64;

    bfc_t acc[2][2];
#pragma unroll
    for (int i = 0; i < 2; i++)
#pragma unroll
        for (int j = 0; j < 2; j++) wmma::fill_fragment(acc[i][j], 0.f);

    for (int k0 = 0; k0 < 1024; k0 += 32) {
#pragma unroll
        for (int l = 0; l < 4; l++) {
            int id = tid + l * 128;
            int r = id >> 3, c4 = (id & 7) * 4;
            int ra = row0 + r - o8;
            float4 v = (ra >= 0)
                ? *(const float4*)(Bold + (size_t)ra * 1024 + k0 + c4)
                : make_float4(0.f, 0.f, 0.f, 0.f);
            bsplit(v.x, Ah[r][c4 + 0], Al[r][c4 + 0]);
            bsplit(v.y, Ah[r][c4 + 1], Al[r][c4 + 1]);
            bsplit(v.z, Ah[r][c4 + 2], Al[r][c4 + 2]);
            bsplit(v.w, Ah[r][c4 + 3], Al[r][c4 + 3]);
        }
#pragma unroll
        for (int l = 0; l < 4; l++) {
            int id = tid + l * 128;
            int r = id >> 3, c4 = (id & 7) * 4;
            float4 v = *(const float4*)(Pm + (size_t)(col0 + r) * 1024 + k0 + c4);
            bsplit(v.x, Bh[r][c4 + 0], Bl[r][c4 + 0]);
            bsplit(v.y, Bh[r][c4 + 1], Bl[r][c4 + 1]);
            bsplit(v.z, Bh[r][c4 + 2], Bl[r][c4 + 2]);
            bsplit(v.w, Bh[r][c4 + 3], Bl[r][c4 + 3]);
        }
        __syncthreads();
#pragma unroll
        for (int kk = 0; kk < 2; kk++) {
            bfa_t ah[2], al[2];
            bfbc_t bh[2], bl[2];
#pragma unroll
            for (int i = 0; i < 2; i++) {
                wmma::load_matrix_sync(ah[i], &Ah[wr * 32 + i * 16][kk * 16], 40);
                wmma::load_matrix_sync(al[i], &Al[wr * 32 + i * 16][kk * 16], 40);
            }
#pragma unroll
            for (int j = 0; j < 2; j++) {
                wmma::load_matrix_sync(bh[j], &Bh[wc * 32 + j * 16][kk * 16], 40);
                wmma::load_matrix_sync(bl[j], &Bl[wc * 32 + j * 16][kk * 16], 40);
            }
#pragma unroll
            for (int i = 0; i < 2; i++)
#pragma unroll
                for (int j = 0; j < 2; j++) {
                    wmma::mma_sync(acc[i][j], ah[i], bh[j], acc[i][j]);
                    wmma::mma_sync(acc[i][j], al[i], bh[j], acc[i][j]);
                    wmma::mma_sync(acc[i][j], ah[i], bl[j], acc[i][j]);
                }
        }
        __syncthreads();
    }
#pragma unroll
    for (int i = 0; i < 2; i++)
#pragma unroll
        for (int j = 0; j < 2; j++)
            wmma::store_matrix_sync(&Cs[wr * 32 + i * 16][wc * 32 + j * 16],
                                    acc[i][j], 68, wmma::mem_row_major);
    __syncthreads();
#pragma unroll
    for (int l = 0; l < 8; l++) {
        int id = tid + l * 128;
        int r = id >> 4, c4 = (id & 15) * 4;
        int rg = row0 + r;
        int col = col0 + c4;
        size_t off = (size_t)rg * 1024 + col;
        float4 bv = *(const float4*)(Bold + off);
        float4 av = *(float4*)&Cs[r][c4];
        av.x += bv.x; av.y += bv.y; av.z += bv.z; av.w += bv.w;
        *(float4*)(Bnew + off) = av;
    }
}

// --------------------------------------------------------------------------
__global__ void k_matvec_c(const float* __restrict__ rc_b)
{
    int e = blockIdx.x * 8 + (threadIdx.x >> 5);
    int lane = threadIdx.x & 31;
    const float* mr = g_M + (size_t)e * 1024;
    float acc = 0.f;
#pragma unroll 4
    for (int d = lane; d < 1024; d += 32) acc += mr[d] * rc_b[d];
#pragma unroll
    for (int o = 16; o > 0; o >>= 1) acc += __shfl_xor_sync(0xffffffffu, acc, o);
    if (lane == 0) g_cvec[e] = acc;
}

// --------------------------------------------------------------------------
// Pipelined bf16 64x64 mainloop (shared by nt_u / pass1 / pass2).
// A rows: per-thread global bf16 hi/lo row pointers (2 rows each, l=0/1).
// B rows: Q or P hi/lo, rows col0+r.
// sm layout per buffer: Ah@0 Al@5120 Bh@10240 Bl@15360; 2 buffers.
#define PIPE_MAIN(AH_PTR, AL_PTR, AOFF_EXPR, BH, BL)                           \
    {                                                                          \
        const int r_[2] = { tid >> 2, (tid + 128) >> 2 };                      \
        const int f_    = (tid & 3) * 8;                                       \
        for (int kc = 0; kc < 32; kc++) {                                      \
            int cur = kc & 1;                                                  \
            if (kc == 0) {                                                     \
                char* bb = sm;                                                 \
                _Pragma("unroll")                                              \
                for (int l = 0; l < 2; l++) {                                  \
                    int r = r_[l];                                             \
                    size_t offa = AOFF_EXPR + f_;                              \
                    size_t offb = (size_t)(col0 + r) * 1024 + f_;              \
                    uint32_t sb = s2u(bb + r * 80 + f_ * 2);                   \
                    CPA16(sb,         AH_PTR + offa);                          \
                    CPA16(sb + 5120,  AL_PTR + offa);                          \
                    CPA16(sb + 10240, BH + offb);                              \
                    CPA16(sb + 15360, BL + offb);                              \
                }                                                              \
                CPA_COMMIT();                                                  \
            }                                                                  \
            if (kc + 1 < 32) {                                                 \
                int k0n = (kc + 1) * 32;                                       \
                char* bb = sm + (cur ^ 1) * PBUF;                              \
                _Pragma("unroll")                                              \
                for (int l = 0; l < 2; l++) {                                  \
                    int r = r_[l];                                             \
                    size_t offa = AOFF_EXPR + k0n + f_;                        \
                    size_t offb = (size_t)(col0 + r) * 1024 + k0n + f_;        \
                    uint32_t sb = s2u(bb + r * 80 + f_ * 2);                   \
                    CPA16(sb,         AH_PTR + offa);                          \
                    CPA16(sb + 5120,  AL_PTR + offa);                          \
                    CPA16(sb + 10240, BH + offb);                              \
                    CPA16(sb + 15360, BL + offb);                              \
                }                                                              \
                CPA_COMMIT();                                                  \
                CPA_WAIT(1);                                                   \
            } else {                                                           \
                CPA_WAIT(0);                                                   \
            }                                                                  \
            __syncthreads();                                                   \
            const __nv_bfloat16 (*Ah_)[40] =                                   \
                (const __nv_bfloat16(*)[40])(sm + cur * PBUF);                 \
            const __nv_bfloat16 (*Al_)[40] =                                   \
                (const __nv_bfloat16(*)[40])(sm + cur * PBUF + 5120);          \
            const __nv_bfloat16 (*Bh_)[40] =                                   \
                (const __nv_bfloat16(*)[40])(sm + cur * PBUF + 10240);         \
            const __nv_bfloat16 (*Bl_)[40] =                                   \
                (const __nv_bfloat16(*)[40])(sm + cur * PBUF + 15360);         \
            _Pragma("unroll")                                                  \
            for (int kk = 0; kk < 2; kk++) {                                   \
                bfa_t ah[2], al[2];                                            \
                bfbc_t bh[2], bl[2];                                           \
                _Pragma("unroll")                                              \
                for (int i = 0; i < 2; i++) {                                  \
                    wmma::load_matrix_sync(ah[i], &Ah_[wr * 32 + i * 16][kk * 16], 40); \
                    wmma::load_matrix_sync(al[i], &Al_[wr * 32 + i * 16][kk * 16], 40); \
                }                                                              \
                _Pragma("unroll")                                              \
                for (int j = 0; j < 2; j++) {                                  \
                    wmma::load_matrix_sync(bh[j], &Bh_[wc * 32 + j * 16][kk * 16], 40); \
                    wmma::load_matrix_sync(bl[j], &Bl_[wc * 32 + j * 16][kk * 16], 40); \
                }                                                              \
                _Pragma("unroll")                                              \
                for (int i = 0; i < 2; i++)                                    \
                    _Pragma("unroll")                                          \
                    for (int j = 0; j < 2; j++) {                              \
                        wmma::mma_sync(acc[i][j], ah[i], bh[j], acc[i][j]);    \
                        wmma::mma_sync(acc[i][j], al[i], bh[j], acc[i][j]);    \
                        wmma::mma_sync(acc[i][j], ah[i], bl[j], acc[i][j]);    \
                    }                                                          \
            }                                                                  \
            __syncthreads();                                                   \
        }                                                                      \
    }

// --------------------------------------------------------------------------
// U GEMM (bf16, NT, pipelined): out[b,t,:] = x[b,t,:] @ P^T + c, t=1..2047.
// CTA 64x64, 128 threads, grid (16, 256).
__global__ void __launch_bounds__(128)
k_nt_u(float* __restrict__ out)
{
    __shared__ __align__(16) char sm[2 * PBUF];
    float (*Cs)[68] = (float(*)[68])sm;

    const int tid  = threadIdx.x;
    const int warp = tid >> 5;
    const int wr   = warp >> 1, wc = warp & 1;
    const int row0 = blockIdx.y * 64, col0 = blockIdx.x * 64;

    bfc_t acc[2][2];
#pragma unroll
    for (int i = 0; i < 2; i++)
#pragma unroll
        for (int j = 0; j < 2; j++) wmma::fill_fragment(acc[i][j], 0.f);

    // per-thread gather offsets for the two staged A rows
    size_t axoff[2];
#pragma unroll
    for (int l = 0; l < 2; l++) {
        int r = (tid + l * 128) >> 2;
        int rg = row0 + r;
        int b = 0, t = 0;
        if (rg < NROW_U) { b = rg / 2047; t = 1 + rg % 2047; }
        axoff[l] = ((size_t)(b * 2048 + t)) * 1024;
    }

    PIPE_MAIN(g_Xh, g_Xl, axoff[l], g_Ph, g_Pl)

#pragma unroll
    for (int i = 0; i < 2; i++)
#pragma unroll
        for (int j = 0; j < 2; j++)
            wmma::store_matrix_sync(&Cs[wr * 32 + i * 16][wc * 32 + j * 16],
                                    acc[i][j], 68, wmma::mem_row_major);
    __syncthreads();
#pragma unroll
    for (int l = 0; l < 8; l++) {
        int id = tid + l * 128;
        int r = id >> 4, c4 = (id & 15) * 4;
        int rg = row0 + r;
        if (rg < NROW_U) {
            int b = rg / 2047, t = 1 + rg % 2047;
            float4 v = *(float4*)&Cs[r][c4];
            int col = col0 + c4;
            v.x += g_cvec[col + 0]; v.y += g_cvec[col + 1];
            v.z += g_cvec[col + 2]; v.w += g_cvec[col + 3];
            *(float4*)(out + ((size_t)(b * 2048 + t)) * 1024 + col) = v;
        }
    }
}

// --------------------------------------------------------------------------
// out[b,0,:] = x[b,0,:] ; V0 rows 0..7 = y_0
__global__ void k_init(const float* __restrict__ x, float* __restrict__ out)
{
    int idx = blockIdx.x * blockDim.x + threadIdx.x;   // 8192
    int b = idx >> 10, e = idx & 1023;
    float v = x[((size_t)b * 2048) * 1024 + e];
    out[((size_t)b * 2048) * 1024 + e] = v;
    g_V0[idx] = v;
}

// --------------------------------------------------------------------------
// Pass 1 step s (pipelined): w <- Q @ w + u_{32k+s}, chunks 0..62.
__global__ void __launch_bounds__(128)
k_pass1(const float* __restrict__ u, int s)
{
    const int wb = s & 1, rbuf = wb ^ 1;
    const __nv_bfloat16* Wih = g_Wsh[rbuf];
    const __nv_bfloat16* Wil = g_Wsl[rbuf];
    __nv_bfloat16* Woh = g_Wsh[wb];
    __nv_bfloat16* Wol = g_Wsl[wb];

    __shared__ __align__(16) char sm[2 * PBUF];
    float (*Cs)[68] = (float(*)[68])sm;

    const int tid  = threadIdx.x;
    const int warp = tid >> 5;
    const int wr   = warp >> 1, wc = warp & 1;
    const int row0 = blockIdx.y * 64, col0 = blockIdx.x * 64;

    bfc_t acc[2][2];
#pragma unroll
    for (int i = 0; i < 2; i++)
#pragma unroll
        for (int j = 0; j < 2; j++) wmma::fill_fragment(acc[i][j], 0.f);

    if (s > 1) {
        size_t aroff[2];
#pragma unroll
        for (int l = 0; l < 2; l++) {
            int r = (tid + l * 128) >> 2;
            int rg = row0 + r;
            aroff[l] = (size_t)((rg < R1) ? rg : 0) * 1024;
        }
        PIPE_MAIN(Wih, Wil, aroff[l], g_Qh, g_Ql)
    }
#pragma unroll
    for (int i = 0; i < 2; i++)
#pragma unroll
        for (int j = 0; j < 2; j++)
            wmma::store_matrix_sync(&Cs[wr * 32 + i * 16][wc * 32 + j * 16],
                                    acc[i][j], 68, wmma::mem_row_major);
    __syncthreads();
#pragma unroll
    for (int l = 0; l < 8; l++) {
        int id = tid + l * 128;
        int r = id >> 4, c4 = (id & 15) * 4;
        int rg = row0 + r;
        if (rg < R1) {
            int ch = rg >> 3, b = rg & 7;
            int t = ch * SCH + s;
            int col = col0 + c4;
            float4 uv = *(const float4*)(u + ((size_t)(b * 2048 + t)) * 1024 + col);
            float4 av = *(float4*)&Cs[r][c4];
            av.x += uv.x; av.y += uv.y; av.z += uv.z; av.w += uv.w;
            size_t soff = (size_t)rg * 1024 + col;
            __nv_bfloat162 hh, ll;
            __nv_bfloat16 h, lo;
            bsplit(av.x, h, lo); hh.x = h; ll.x = lo;
            bsplit(av.y, h, lo); hh.y = h; ll.y = lo;
            *(__nv_bfloat162*)(Woh + soff)     = hh;
            *(__nv_bfloat162*)(Wol + soff)     = ll;
            bsplit(av.z, h, lo); hh.x = h; ll.x = lo;
            bsplit(av.w, h, lo); hh.y = h; ll.y = lo;
            *(__nv_bfloat162*)(Woh + soff + 2) = hh;
            *(__nv_bfloat162*)(Wol + soff + 2) = ll;
            if (s == SCH)
                *(float4*)(g_V0 + (size_t)(rg + 8) * 1024 + col) = av;
        }
    }
}

// --------------------------------------------------------------------------
// Pass 2 step s (pipelined): y_{32k+s} = u + Q y_{32k+s-1}, in place in out.
__global__ void __launch_bounds__(128)
k_pass2(float* __restrict__ y, int s)
{
    const int rbuf = s & 1, wb = rbuf ^ 1;
    const __nv_bfloat16* Yih = g_Ysh[rbuf];
    const __nv_bfloat16* Yil = g_Ysl[rbuf];
    __nv_bfloat16* Yoh = g_Ysh[wb];
    __nv_bfloat16* Yol = g_Ysl[wb];

    __shared__ __align__(16) char sm[2 * PBUF];
    float (*Cs)[68] = (float(*)[68])sm;

    const int tid  = threadIdx.x;
    const int warp = tid >> 5;
    const int wr   = warp >> 1, wc = warp & 1;
    const int row0 = blockIdx.y * 64, col0 = blockIdx.x * 64;

    bfc_t acc[2][2];
#pragma unroll
    for (int i = 0; i < 2; i++)
#pragma unroll
        for (int j = 0; j < 2; j++) wmma::fill_fragment(acc[i][j], 0.f);

    {
        size_t aroff[2];
#pragma unroll
        for (int l = 0; l < 2; l++) {
            int r = (tid + l * 128) >> 2;
            aroff[l] = (size_t)(row0 + r) * 1024;
        }
        PIPE_MAIN(Yih, Yil, aroff[l], g_Qh, g_Ql)
    }
#pragma unroll
    for (int i = 0; i < 2; i++)
#pragma unroll
        for (int j = 0; j < 2; j++)
            wmma::store_matrix_sync(&Cs[wr * 32 + i * 16][wc * 32 + j * 16],
                                    acc[i][j], 68, wmma::mem_row_major);
    __syncthreads();
#pragma unroll
    for (int l = 0; l < 8; l++) {
        int id = tid + l * 128;
        int r = id >> 4, c4 = (id & 15) * 4;
        int rg = row0 + r;
        int ch = rg >> 3, b = rg & 7;
        int t = ch * SCH + s;
        if (t < LSEQ) {
            int col = col0 + c4;
            float* yp = y + ((size_t)(b * 2048 + t)) * 1024 + col;
            float4 yv = *(float4*)yp;
            float4 av = *(float4*)&Cs[r][c4];
            yv.x += av.x; yv.y += av.y; yv.z += av.z; yv.w += av.w;
            *(float4*)yp = yv;
            size_t soff = (size_t)rg * 1024 + col;
            __nv_bfloat162 hh, ll;
            __nv_bfloat16 h, lo;
            bsplit(yv.x, h, lo); hh.x = h; ll.x = lo;
            bsplit(yv.y, h, lo); hh.y = h; ll.y = lo;
            *(__nv_bfloat162*)(Yoh + soff)     = hh;
            *(__nv_bfloat162*)(Yol + soff)     = ll;
            bsplit(yv.z, h, lo); hh.x = h; ll.x = lo;
            bsplit(yv.w, h, lo); hh.y = h; ll.y = lo;
            *(__nv_bfloat162*)(Yoh + soff + 2) = hh;
            *(__nv_bfloat162*)(Yol + soff + 2) = ll;
        }
    }
}

// --------------------------------------------------------------------------
extern "C" void kernel_launch(void* const* d_in, const int* in_sizes, int n_in,
                              void* d_out, int out_size)
{
    const float* x    = (const float*)d_in[0];
    const float* A_w  = (const float*)d_in[1];
    const float* C_w  = (const float*)d_in[2];
    const float* rc_w = (const float*)d_in[3];
    const float* rc_b = (const float*)d_in[4];
    float* out = (float*)d_out;

    dim3 gsq(16, 16);       // 1024x1024 NN: 16x16 tiles of 64x64
    dim3 gps(16, 8);        // pass/scan kernels: 16 col-tiles x 8 row-tiles

    k_prep_wy<<<4096, 256>>>(rc_w);
    k_split_x<<<65536, 256>>>(x);
    // M = C_w @ A_w
    k_nn<<<gsq, 128>>>(C_w, A_w, -1, -1, BUF_M, 1024);
    // P = M @ Wx (Wx = rc_w[:, :1024], ldb = 3072)
    k_nn<<<gsq, 128>>>(0, rc_w, BUF_M, -1, BUF_P, 3072);
    k_split<<<4096, 256>>>(0);
    // Q = M @ Wy
    k_nn<<<gsq, 128>>>(0, 0, BUF_M, BUF_WY, BUF_Q, 1024);
    k_split<<<4096, 256>>>(1);
    // c = M @ rc_b
    k_matvec_c<<<128, 256>>>(rc_b);
    // U into d_out (t = 1..2047)
    k_nt_u<<<dim3(16, 256), 128>>>(out);
    // Q^32 via 5 squarings
    k_nn<<<gsq, 128>>>(0, 0, BUF_Q,  BUF_Q,  BUF_T1, 1024);
    k_nn<<<gsq, 128>>>(0, 0, BUF_T1, BUF_T1, BUF_T2, 1024);
    k_nn<<<gsq, 128>>>(0, 0, BUF_T2, BUF_T2, BUF_T1, 1024);
    k_nn<<<gsq, 128>>>(0, 0, BUF_T1, BUF_T1, BUF_T2, 1024);
    k_nn<<<gsq, 128>>>(0, 0, BUF_T2, BUF_T2, BUF_QS, 1024);
    // y_0 -> out and V0 rows 0..7
    k_init<<<32, 256>>>(x, out);
    // pass 1 (s==32 deposits chunk-end sums into V0 rows 8..511)
    for (int s = 1; s <= SCH; s++)
        k_pass1<<<gps, 128>>>(out, s);
    // Kogge-Stone carry scan: offsets 1,2,4,8,16,32 (powers of Q^32)
    k_scan<<<gps, 128>>>(0, BUF_QS, 8);                       // V0->V1, o=1
    k_nn<<<gsq, 128>>>(0, 0, BUF_QS, BUF_QS, BUF_T1, 1024);   // T1 = Q^64
    k_scan<<<gps, 128>>>(1, BUF_T1, 16);                      // V1->V0, o=2
    k_nn<<<gsq, 128>>>(0, 0, BUF_T1, BUF_T1, BUF_T2, 1024);   // T2 = Q^128
    k_scan<<<gps, 128>>>(0, BUF_T2, 32);                      // V0->V1, o=4
    k_nn<<<gsq, 128>>>(0, 0, BUF_T2, BUF_T2, BUF_T1, 1024);   // T1 = Q^256
    k_scan<<<gps, 128>>>(1, BUF_T1, 64);                      // V1->V0, o=8
    k_nn<<<gsq, 128>>>(0, 0, BUF_T1, BUF_T1, BUF_T2, 1024);   // T2 = Q^512
    k_scan<<<gps, 128>>>(0, BUF_T2, 128);                     // V0->V1, o=16
    k_nn<<<gsq, 128>>>(0, 0, BUF_T2, BUF_T2, BUF_T1, 1024);   // T1 = Q^1024
    k_scan<<<gps, 128>>>(1, BUF_T1, 256);                     // V1->V0, o=32
    // seed pass-2 state from scanned carries (V0)
    k_seed<<<2048, 256>>>();
    // pass 2
    for (int s = 1; s <= SCH; s++)
        k_pass2<<<gps, 128>>>(out, s);
}

// round 16
// speedup vs baseline: 3.0213x; 1.0319x over previous
#include <cuda_runtime.h>
#include <cuda_bf16.h>
#include <mma.h>
#include <cstddef>
#include <cstdint>

using namespace nvcuda;

// ---------------------------------------------------------------------------
// S4Layer: B=8, L=2048, D=1024. Chunked scan: 64 chunks of S=32.
// GEMMs: bf16 tensor MMA m16n16k16, 2-term split (hi*hi + lo*hi + hi*lo).
// Carry chain: 6-round Kogge-Stone matrix scan.
// All hot GEMMs (pass1/pass2/nt_u/pow/scan): pre-split bf16 operands +
// cp.async double-buffered smem pipeline. fp32 only at prep and epilogues.
// ---------------------------------------------------------------------------

#define DM 1024
#define NB 8
#define LSEQ 2048
#define SCH 32
#define NCH 64
#define R1 504                     // pass-1 rows = 63 chunks * 8 batch
#define R2 512                     // pass-2 rows = 64 chunks * 8 batch
#define NROW_U (NB * (LSEQ - 1))   // 16376

__device__ float g_M [DM * DM];
__device__ float g_P [DM * DM];
__device__ float g_Q [DM * DM];
__device__ float g_Wy[DM * DM];
__device__ float g_cvec[DM];
__device__ float g_V0[R2 * DM];    // carry-scan state (fp32), double-buffered
__device__ float g_V1[R2 * DM];

// pre-split bf16 hi/lo operands and states
__device__ __nv_bfloat16 g_Ph[DM * DM],  g_Pl[DM * DM];
__device__ __nv_bfloat16 g_Qh[DM * DM],  g_Ql[DM * DM];
__device__ __nv_bfloat16 g_T1h[DM * DM], g_T1l[DM * DM];
__device__ __nv_bfloat16 g_T2h[DM * DM], g_T2l[DM * DM];
__device__ __nv_bfloat16 g_QSh[DM * DM], g_QSl[DM * DM];
__device__ __nv_bfloat16 g_Xh[NB * LSEQ * DM], g_Xl[NB * LSEQ * DM];
__device__ __nv_bfloat16 g_Wsh[2][R1 * DM], g_Wsl[2][R1 * DM];  // pass1 state
__device__ __nv_bfloat16 g_Ysh[2][R2 * DM], g_Ysl[2][R2 * DM];  // pass2 state
__device__ __nv_bfloat16 g_Vh[2][R2 * DM],  g_Vl[2][R2 * DM];   // scan state

#define BUF_M  0
#define BUF_P  1
#define BUF_Q  2
#define BUF_WY 3

__device__ __forceinline__ float* sel_buf(int i)
{
    switch (i) {
        case BUF_M:  return g_M;
        case BUF_P:  return g_P;
        case BUF_Q:  return g_Q;
        default:     return g_Wy;
    }
}

// bf16 pair selectors (powers)
#define PW_Q  0
#define PW_T1 1
#define PW_T2 2
#define PW_QS 3
__device__ __forceinline__ __nv_bfloat16* sel_h(int i)
{
    switch (i) {
        case PW_Q:  return g_Qh;
        case PW_T1: return g_T1h;
        case PW_T2: return g_T2h;
        default:    return g_QSh;
    }
}
__device__ __forceinline__ __nv_bfloat16* sel_l(int i)
{
    switch (i) {
        case PW_Q:  return g_Ql;
        case PW_T1: return g_T1l;
        case PW_T2: return g_T2l;
        default:    return g_QSl;
    }
}

typedef wmma::fragment<wmma::matrix_a, 16, 16, 16, __nv_bfloat16, wmma::row_major> bfa_t;
typedef wmma::fragment<wmma::matrix_b, 16, 16, 16, __nv_bfloat16, wmma::col_major> bfbc_t;
typedef wmma::fragment<wmma::matrix_b, 16, 16, 16, __nv_bfloat16, wmma::row_major> bfbr_t;
typedef wmma::fragment<wmma::accumulator, 16, 16, 16, float> bfc_t;

__device__ __forceinline__ void bsplit(float v, __nv_bfloat16& h, __nv_bfloat16& l)
{
    __nv_bfloat16 hb = __float2bfloat16(v);
    h = hb;
    l = __float2bfloat16(v - __bfloat162float(hb));
}

__device__ __forceinline__ uint32_t s2u(const void* p)
{
    uint32_t a;
    asm("{ .reg .u64 t; cvta.to.shared.u64 t, %1; cvt.u32.u64 %0, t; }"
        : "=r"(a) : "l"(p));
    return a;
}
#define CPA16(s, g)      asm volatile("cp.async.ca.shared.global [%0], [%1], 16;" :: "r"(s), "l"(g))
#define CPA16Z(s, g, sz) asm volatile("cp.async.ca.shared.global [%0], [%1], 16, %2;" :: "r"(s), "l"(g), "r"(sz))
#define CPA_COMMIT()     asm volatile("cp.async.commit_group;" ::: "memory")
#define CPA_WAIT(n)      asm volatile("cp.async.wait_group %0;" :: "n"(n) : "memory")

// per-buffer smem layout for pipelined 64x64 kernels (bytes):
//   Ah @ 0, Al @ 5120, Bh @ 10240, Bl @ 15360  (each 64 x 40 bf16 = 5120 B)
#define PBUF 20480

// --------------------------------------------------------------------------
__global__ void k_prep_wy(const float* __restrict__ rc_w)
{
    int idx = blockIdx.x * blockDim.x + threadIdx.x;   // 1M
    int k = idx >> 10, d = idx & 1023;
    g_Wy[idx] = rc_w[k * 3072 + 1024 + d] + rc_w[k * 3072 + 2048 + d];
}

__global__ void k_split(int which)
{
    int idx = blockIdx.x * blockDim.x + threadIdx.x;   // 1M
    float v = which ? g_Q[idx] : g_P[idx];
    if (which) bsplit(v, g_Qh[idx], g_Ql[idx]);
    else       bsplit(v, g_Ph[idx], g_Pl[idx]);
}

__global__ void k_split_x(const float* __restrict__ x)
{
    int idx = blockIdx.x * blockDim.x + threadIdx.x;   // 16.7M
    bsplit(x[idx], g_Xh[idx], g_Xl[idx]);
}

__global__ void k_seed()
{
    int idx = blockIdx.x * blockDim.x + threadIdx.x;   // 524288
    bsplit(g_V0[idx], g_Ysh[1][idx], g_Ysl[1][idx]);
}

// --------------------------------------------------------------------------
// NN GEMM (prep only): C[1024,1024] = A @ B (row-major, B ld = ldb).
__global__ void __launch_bounds__(128)
k_nn(const float* extA, const float* extB, int ia, int ib, int ic, int ldb)
{
    const float* A  = (ia >= 0) ? sel_buf(ia) : extA;
    const float* Bm = (ib >= 0) ? sel_buf(ib) : extB;
    float*       Cm = sel_buf(ic);

    __shared__ __align__(16) __nv_bfloat16 Ah[64][40];
    __shared__ __align__(16) __nv_bfloat16 Al[64][40];
    __shared__ __align__(16) __nv_bfloat16 Bh[32][72];
    __shared__ __align__(16) __nv_bfloat16 Bl[32][72];

    const int tid  = threadIdx.x;
    const int warp = tid >> 5;
    const int wr   = warp >> 1, wc = warp & 1;
    const int row0 = blockIdx.y * 64, col0 = blockIdx.x * 64;

    bfc_t acc[2][2];
#pragma unroll
    for (int i = 0; i < 2; i++)
#pragma unroll
        for (int j = 0; j < 2; j++) wmma::fill_fragment(acc[i][j], 0.f);

    for (int k0 = 0; k0 < 1024; k0 += 32) {
#pragma unroll
        for (int l = 0; l < 4; l++) {
            int id = tid + l * 128;
            int r = id >> 3, c4 = (id & 7) * 4;
            float4 v = *(const float4*)(A + (size_t)(row0 + r) * 1024 + k0 + c4);
            bsplit(v.x, Ah[r][c4 + 0], Al[r][c4 + 0]);
            bsplit(v.y, Ah[r][c4 + 1], Al[r][c4 + 1]);
            bsplit(v.z, Ah[r][c4 + 2], Al[r][c4 + 2]);
            bsplit(v.w, Ah[r][c4 + 3], Al[r][c4 + 3]);
        }
#pragma unroll
        for (int l = 0; l < 4; l++) {
            int id = tid + l * 128;
            int k = id >> 4, n4 = (id & 15) * 4;
            float4 v = *(const float4*)(Bm + (size_t)(k0 + k) * ldb + col0 + n4);
            bsplit(v.x, Bh[k][n4 + 0], Bl[k][n4 + 0]);
            bsplit(v.y, Bh[k][n4 + 1], Bl[k][n4 + 1]);
            bsplit(v.z, Bh[k][n4 + 2], Bl[k][n4 + 2]);
            bsplit(v.w, Bh[k][n4 + 3], Bl[k][n4 + 3]);
        }
        __syncthreads();
#pragma unroll
        for (int kk = 0; kk < 2; kk++) {
            bfa_t ah[2], al[2];
            bfbr_t bh[2], bl[2];
#pragma unroll
            for (int i = 0; i < 2; i++) {
                wmma::load_matrix_sync(ah[i], &Ah[wr * 32 + i * 16][kk * 16], 40);
                wmma::load_matrix_sync(al[i], &Al[wr * 32 + i * 16][kk * 16], 40);
            }
#pragma unroll
            for (int j = 0; j < 2; j++) {
                wmma::load_matrix_sync(bh[j], &Bh[kk * 16][wc * 32 + j * 16], 72);
                wmma::load_matrix_sync(bl[j], &Bl[kk * 16][wc * 32 + j * 16], 72);
            }
#pragma unroll
            for (int i = 0; i < 2; i++)
#pragma unroll
                for (int j = 0; j < 2; j++) {
                    wmma::mma_sync(acc[i][j], ah[i], bh[j], acc[i][j]);
                    wmma::mma_sync(acc[i][j], al[i], bh[j], acc[i][j]);
                    wmma::mma_sync(acc[i][j], ah[i], bl[j], acc[i][j]);
                }
        }
        __syncthreads();
    }
#pragma unroll
    for (int i = 0; i < 2; i++)
#pragma unroll
        for (int j = 0; j < 2; j++)
            wmma::store_matrix_sync(
                Cm + (size_t)(row0 + wr * 32 + i * 16) * 1024 + col0 + wc * 32 + j * 16,
                acc[i][j], 1024, wmma::mem_row_major);
}

// --------------------------------------------------------------------------
// Pipelined squaring on bf16 pairs: C = M @ M, in/out pre-split hi/lo.
// CTA 64x64, 128 threads, grid (16,16).
// Stage layout: Ah@0(5120) Al@5120 Bh@10240(4608) Bl@14848; stage = 19456.
#define QBUF 19456
__global__ void __launch_bounds__(128)
k_pow(int isrc, int idst)
{
    const __nv_bfloat16* Mh = sel_h(isrc);
    const __nv_bfloat16* Ml = sel_l(isrc);
    __nv_bfloat16* Ch = sel_h(idst);
    __nv_bfloat16* Cl = sel_l(idst);

    __shared__ __align__(16) char sm[2 * QBUF];
    float (*Cs)[68] = (float(*)[68])sm;

    const int tid  = threadIdx.x;
    const int warp = tid >> 5;
    const int wr   = warp >> 1, wc = warp & 1;
    const int row0 = blockIdx.y * 64, col0 = blockIdx.x * 64;

    bfc_t acc[2][2];
#pragma unroll
    for (int i = 0; i < 2; i++)
#pragma unroll
        for (int j = 0; j < 2; j++) wmma::fill_fragment(acc[i][j], 0.f);

    const int ar_[2] = { tid >> 2, (tid + 128) >> 2 };   // 0..63
    const int af_    = (tid & 3) * 8;
    const int bk_[2] = { tid >> 3, (tid + 128) >> 3 };   // 0..31
    const int bn_    = (tid & 7) * 8;

    for (int kc = 0; kc < 32; kc++) {
        int cur = kc & 1;
        if (kc == 0) {
            char* bb = sm;
#pragma unroll
            for (int l = 0; l < 2; l++) {
                int r = ar_[l];
                size_t offa = (size_t)(row0 + r) * 1024 + af_;
                uint32_t sa = s2u(bb + r * 80 + af_ * 2);
                CPA16(sa,        Mh + offa);
                CPA16(sa + 5120, Ml + offa);
                int k = bk_[l];
                size_t offb = (size_t)k * 1024 + col0 + bn_;
                uint32_t sb = s2u(bb + 10240 + k * 144 + bn_ * 2);
                CPA16(sb,        Mh + offb);
                CPA16(sb + 4608, Ml + offb);
            }
            CPA_COMMIT();
        }
        if (kc + 1 < 32) {
            int k0n = (kc + 1) * 32;
            char* bb = sm + (cur ^ 1) * QBUF;
#pragma unroll
            for (int l = 0; l < 2; l++) {
                int r = ar_[l];
                size_t offa = (size_t)(row0 + r) * 1024 + k0n + af_;
                uint32_t sa = s2u(bb + r * 80 + af_ * 2);
                CPA16(sa,        Mh + offa);
                CPA16(sa + 5120, Ml + offa);
                int k = bk_[l];
                size_t offb = (size_t)(k0n + k) * 1024 + col0 + bn_;
                uint32_t sb = s2u(bb + 10240 + k * 144 + bn_ * 2);
                CPA16(sb,        Mh + offb);
                CPA16(sb + 4608, Ml + offb);
            }
            CPA_COMMIT();
            CPA_WAIT(1);
        } else {
            CPA_WAIT(0);
        }
        __syncthreads();
        const __nv_bfloat16 (*Ah_)[40] = (const __nv_bfloat16(*)[40])(sm + cur * QBUF);
        const __nv_bfloat16 (*Al_)[40] = (const __nv_bfloat16(*)[40])(sm + cur * QBUF + 5120);
        const __nv_bfloat16 (*Bh_)[72] = (const __nv_bfloat16(*)[72])(sm + cur * QBUF + 10240);
        const __nv_bfloat16 (*Bl_)[72] = (const __nv_bfloat16(*)[72])(sm + cur * QBUF + 14848);
#pragma unroll
        for (int kk = 0; kk < 2; kk++) {
            bfa_t ah[2], al[2];
            bfbr_t bh[2], bl[2];
#pragma unroll
            for (int i = 0; i < 2; i++) {
                wmma::load_matrix_sync(ah[i], &Ah_[wr * 32 + i * 16][kk * 16], 40);
                wmma::load_matrix_sync(al[i], &Al_[wr * 32 + i * 16][kk * 16], 40);
            }
#pragma unroll
            for (int j = 0; j < 2; j++) {
                wmma::load_matrix_sync(bh[j], &Bh_[kk * 16][wc * 32 + j * 16], 72);
                wmma::load_matrix_sync(bl[j], &Bl_[kk * 16][wc * 32 + j * 16], 72);
            }
#pragma unroll
            for (int i = 0; i < 2; i++)
#pragma unroll
                for (int j = 0; j < 2; j++) {
                    wmma::mma_sync(acc[i][j], ah[i], bh[j], acc[i][j]);
                    wmma::mma_sync(acc[i][j], al[i], bh[j], acc[i][j]);
                    wmma::mma_sync(acc[i][j], ah[i], bl[j], acc[i][j]);
                }
        }
        __syncthreads();
    }
#pragma unroll
    for (int i = 0; i < 2; i++)
#pragma unroll
        for (int j = 0; j < 2; j++)
            wmma::store_matrix_sync(&Cs[wr * 32 + i * 16][wc * 32 + j * 16],
                                    acc[i][j], 68, wmma::mem_row_major);
    __syncthreads();
#pragma unroll
    for (int l = 0; l < 8; l++) {
        int id = tid + l * 128;
        int r = id >> 4, c4 = (id & 15) * 4;
        float4 v = *(float4*)&Cs[r][c4];
        size_t off = (size_t)(row0 + r) * 1024 + col0 + c4;
        __nv_bfloat162 hh, ll;
        __nv_bfloat16 h, lo;
        bsplit(v.x, h, lo); hh.x = h; ll.x = lo;
        bsplit(v.y, h, lo); hh.y = h; ll.y = lo;
        *(__nv_bfloat162*)(Ch + off)     = hh;
        *(__nv_bfloat162*)(Cl + off)     = ll;
        bsplit(v.z, h, lo); hh.x = h; ll.x = lo;
        bsplit(v.w, h, lo); hh.y = h; ll.y = lo;
        *(__nv_bfloat162*)(Ch + off + 2) = hh;
        *(__nv_bfloat162*)(Cl + off + 2) = ll;
    }
}

// --------------------------------------------------------------------------
// Pipelined Kogge-Stone scan round: Bnew[r] = Bold[r] + Bold[r-o8] @ Pm^T.
// A from bf16 V-state mirror (zfill below row 0), B from pre-split power.
// dir: 0 = V0->V1, 1 = V1->V0. grid (16,8), 128 threads.
__global__ void __launch_bounds__(128)
k_scan(int dir, int ipw, int o8)
{
    const float* Bold = dir ? g_V1 : g_V0;
    float*       Bnew = dir ? g_V0 : g_V1;
    const __nv_bfloat16* Avh = g_Vh[dir];
    const __nv_bfloat16* Avl = g_Vl[dir];
    __nv_bfloat16* Wvh = g_Vh[dir ^ 1];
    __nv_bfloat16* Wvl = g_Vl[dir ^ 1];
    const __nv_bfloat16* Pmh = sel_h(ipw);
    const __nv_bfloat16* Pml = sel_l(ipw);

    __shared__ __align__(16) char sm[2 * PBUF];
    float (*Cs)[68] = (float(*)[68])sm;

    const int tid  = threadIdx.x;
    const int warp = tid >> 5;
    const int wr   = warp >> 1, wc = warp & 1;
    const int row0 = blockIdx.y * 64, col0 = blockIdx.x * 64;

    bfc_t acc[2][2];
#pragma unroll
    for (int i = 0; i < 2; i++)
#pragma unroll
        for (int j = 0; j < 2; j++) wmma::fill_fragment(acc[i][j], 0.f);

    const int r_[2] = { tid >> 2, (tid + 128) >> 2 };
    const int f_    = (tid & 3) * 8;
    int ra_[2]; uint32_t sz_[2]; size_t abase_[2];
#pragma unroll
    for (int l = 0; l < 2; l++) {
        ra_[l] = row0 + r_[l] - o8;
        sz_[l] = (ra_[l] >= 0) ? 16u : 0u;
        abase_[l] = (size_t)((ra_[l] >= 0) ? ra_[l] : 0) * 1024;
    }

    for (int kc = 0; kc < 32; kc++) {
        int cur = kc & 1;
        if (kc == 0) {
            char* bb = sm;
#pragma unroll
            for (int l = 0; l < 2; l++) {
                int r = r_[l];
                size_t offa = abase_[l] + f_;
                size_t offb = (size_t)(col0 + r) * 1024 + f_;
                uint32_t sb = s2u(bb + r * 80 + f_ * 2);
                CPA16Z(sb,        Avh + offa, sz_[l]);
                CPA16Z(sb + 5120, Avl + offa, sz_[l]);
                CPA16(sb + 10240, Pmh + offb);
                CPA16(sb + 15360, Pml + offb);
            }
            CPA_COMMIT();
        }
        if (kc + 1 < 32) {
            int k0n = (kc + 1) * 32;
            char* bb = sm + (cur ^ 1) * PBUF;
#pragma unroll
            for (int l = 0; l < 2; l++) {
                int r = r_[l];
                size_t offa = abase_[l] + k0n + f_;
                size_t offb = (size_t)(col0 + r) * 1024 + k0n + f_;
                uint32_t sb = s2u(bb + r * 80 + f_ * 2);
                CPA16Z(sb,        Avh + offa, sz_[l]);
                CPA16Z(sb + 5120, Avl + offa, sz_[l]);
                CPA16(sb + 10240, Pmh + offb);
                CPA16(sb + 15360, Pml + offb);
            }
            CPA_COMMIT();
            CPA_WAIT(1);
        } else {
            CPA_WAIT(0);
        }
        __syncthreads();
        const __nv_bfloat16 (*Ah_)[40] = (const __nv_bfloat16(*)[40])(sm + cur * PBUF);
        const __nv_bfloat16 (*Al_)[40] = (const __nv_bfloat16(*)[40])(sm + cur * PBUF + 5120);
        const __nv_bfloat16 (*Bh_)[40] = (const __nv_bfloat16(*)[40])(sm + cur * PBUF + 10240);
        const __nv_bfloat16 (*Bl_)[40] = (const __nv_bfloat16(*)[40])(sm + cur * PBUF + 15360);
#pragma unroll
        for (int kk = 0; kk < 2; kk++) {
            bfa_t ah[2], al[2];
            bfbc_t bh[2], bl[2];
#pragma unroll
            for (int i = 0; i < 2; i++) {
                wmma::load_matrix_sync(ah[i], &Ah_[wr * 32 + i * 16][kk * 16], 40);
                wmma::load_matrix_sync(al[i], &Al_[wr * 32 + i * 16][kk * 16], 40);
            }
#pragma unroll
            for (int j = 0; j < 2; j++) {
                wmma::load_matrix_sync(bh[j], &Bh_[wc * 32 + j * 16][kk * 16], 40);
                wmma::load_matrix_sync(bl[j], &Bl_[wc * 32 + j * 16][kk * 16], 40);
            }
#pragma unroll
            for (int i = 0; i < 2; i++)
#pragma unroll
                for (int j = 0; j < 2; j++) {
                    wmma::mma_sync(acc[i][j], ah[i], bh[j], acc[i][j]);
                    wmma::mma_sync(acc[i][j], al[i], bh[j], acc[i][j]);
                    wmma::mma_sync(acc[i][j], ah[i], bl[j], acc[i][j]);
                }
        }
        __syncthreads();
    }
#pragma unroll
    for (int i = 0; i < 2; i++)
#pragma unroll
        for (int j = 0; j < 2; j++)
            wmma::store_matrix_sync(&Cs[wr * 32 + i * 16][wc * 32 + j * 16],
                                    acc[i][j], 68, wmma::mem_row_major);
    __syncthreads();
#pragma unroll
    for (int l = 0; l < 8; l++) {
        int id = tid + l * 128;
        int r = id >> 4, c4 = (id & 15) * 4;
        size_t off = (size_t)(row0 + r) * 1024 + col0 + c4;
        float4 bv = *(const float4*)(Bold + off);
        float4 av = *(float4*)&Cs[r][c4];
        av.x += bv.x; av.y += bv.y; av.z += bv.z; av.w += bv.w;
        *(float4*)(Bnew + off) = av;
        __nv_bfloat162 hh, ll;
        __nv_bfloat16 h, lo;
        bsplit(av.x, h, lo); hh.x = h; ll.x = lo;
        bsplit(av.y, h, lo); hh.y = h; ll.y = lo;
        *(__nv_bfloat162*)(Wvh + off)     = hh;
        *(__nv_bfloat162*)(Wvl + off)     = ll;
        bsplit(av.z, h, lo); hh.x = h; ll.x = lo;
        bsplit(av.w, h, lo); hh.y = h; ll.y = lo;
        *(__nv_bfloat162*)(Wvh + off + 2) = hh;
        *(__nv_bfloat162*)(Wvl + off + 2) = ll;
    }
}

// --------------------------------------------------------------------------
__global__ void k_matvec_c(const float* __restrict__ rc_b)
{
    int e = blockIdx.x * 8 + (threadIdx.x >> 5);
    int lane = threadIdx.x & 31;
    const float* mr = g_M + (size_t)e * 1024;
    float acc = 0.f;
#pragma unroll 4
    for (int d = lane; d < 1024; d += 32) acc += mr[d] * rc_b[d];
#pragma unroll
    for (int o = 16; o > 0; o >>= 1) acc += __shfl_xor_sync(0xffffffffu, acc, o);
    if (lane == 0) g_cvec[e] = acc;
}

// --------------------------------------------------------------------------
// Pipelined bf16 64x64 mainloop (shared by nt_u / pass1 / pass2).
#define PIPE_MAIN(AH_PTR, AL_PTR, AOFF_EXPR, BH, BL)                           \
    {                                                                          \
        const int r_[2] = { tid >> 2, (tid + 128) >> 2 };                      \
        const int f_    = (tid & 3) * 8;                                       \
        for (int kc = 0; kc < 32; kc++) {                                      \
            int cur = kc & 1;                                                  \
            if (kc == 0) {                                                     \
                char* bb = sm;                                                 \
                _Pragma("unroll")                                              \
                for (int l = 0; l < 2; l++) {                                  \
                    int r = r_[l];                                             \
                    size_t offa = AOFF_EXPR + f_;                              \
                    size_t offb = (size_t)(col0 + r) * 1024 + f_;              \
                    uint32_t sb = s2u(bb + r * 80 + f_ * 2);                   \
                    CPA16(sb,         AH_PTR + offa);                          \
                    CPA16(sb + 5120,  AL_PTR + offa);                          \
                    CPA16(sb + 10240, BH + offb);                              \
                    CPA16(sb + 15360, BL + offb);                              \
                }                                                              \
                CPA_COMMIT();                                                  \
            }                                                                  \
            if (kc + 1 < 32) {                                                 \
                int k0n = (kc + 1) * 32;                                       \
                char* bb = sm + (cur ^ 1) * PBUF;                              \
                _Pragma("unroll")                                              \
                for (int l = 0; l < 2; l++) {                                  \
                    int r = r_[l];                                             \
                    size_t offa = AOFF_EXPR + k0n + f_;                        \
                    size_t offb = (size_t)(col0 + r) * 1024 + k0n + f_;        \
                    uint32_t sb = s2u(bb + r * 80 + f_ * 2);                   \
                    CPA16(sb,         AH_PTR + offa);                          \
                    CPA16(sb + 5120,  AL_PTR + offa);                          \
                    CPA16(sb + 10240, BH + offb);                              \
                    CPA16(sb + 15360, BL + offb);                              \
                }                                                              \
                CPA_COMMIT();                                                  \
                CPA_WAIT(1);                                                   \
            } else {                                                           \
                CPA_WAIT(0);                                                   \
            }                                                                  \
            __syncthreads();                                                   \
            const __nv_bfloat16 (*Ah_)[40] =                                   \
                (const __nv_bfloat16(*)[40])(sm + cur * PBUF);                 \
            const __nv_bfloat16 (*Al_)[40] =                                   \
                (const __nv_bfloat16(*)[40])(sm + cur * PBUF + 5120);          \
            const __nv_bfloat16 (*Bh_)[40] =                                   \
                (const __nv_bfloat16(*)[40])(sm + cur * PBUF + 10240);         \
            const __nv_bfloat16 (*Bl_)[40] =                                   \
                (const __nv_bfloat16(*)[40])(sm + cur * PBUF + 15360);         \
            _Pragma("unroll")                                                  \
            for (int kk = 0; kk < 2; kk++) {                                   \
                bfa_t ah[2], al[2];                                            \
                bfbc_t bh[2], bl[2];                                           \
                _Pragma("unroll")                                              \
                for (int i = 0; i < 2; i++) {                                  \
                    wmma::load_matrix_sync(ah[i], &Ah_[wr * 32 + i * 16][kk * 16], 40); \
                    wmma::load_matrix_sync(al[i], &Al_[wr * 32 + i * 16][kk * 16], 40); \
                }                                                              \
                _Pragma("unroll")                                              \
                for (int j = 0; j < 2; j++) {                                  \
                    wmma::load_matrix_sync(bh[j], &Bh_[wc * 32 + j * 16][kk * 16], 40); \
                    wmma::load_matrix_sync(bl[j], &Bl_[wc * 32 + j * 16][kk * 16], 40); \
                }                                                              \
                _Pragma("unroll")                                              \
                for (int i = 0; i < 2; i++)                                    \
                    _Pragma("unroll")                                          \
                    for (int j = 0; j < 2; j++) {                              \
                        wmma::mma_sync(acc[i][j], ah[i], bh[j], acc[i][j]);    \
                        wmma::mma_sync(acc[i][j], al[i], bh[j], acc[i][j]);    \
                        wmma::mma_sync(acc[i][j], ah[i], bl[j], acc[i][j]);    \
                    }                                                          \
            }                                                                  \
            __syncthreads();                                                   \
        }                                                                      \
    }

// --------------------------------------------------------------------------
// U GEMM (bf16, NT, pipelined): out[b,t,:] = x[b,t,:] @ P^T + c, t=1..2047.
__global__ void __launch_bounds__(128)
k_nt_u(float* __restrict__ out)
{
    __shared__ __align__(16) char sm[2 * PBUF];
    float (*Cs)[68] = (float(*)[68])sm;

    const int tid  = threadIdx.x;
    const int warp = tid >> 5;
    const int wr   = warp >> 1, wc = warp & 1;
    const int row0 = blockIdx.y * 64, col0 = blockIdx.x * 64;

    bfc_t acc[2][2];
#pragma unroll
    for (int i = 0; i < 2; i++)
#pragma unroll
        for (int j = 0; j < 2; j++) wmma::fill_fragment(acc[i][j], 0.f);

    size_t axoff[2];
#pragma unroll
    for (int l = 0; l < 2; l++) {
        int r = (tid + l * 128) >> 2;
        int rg = row0 + r;
        int b = 0, t = 0;
        if (rg < NROW_U) { b = rg / 2047; t = 1 + rg % 2047; }
        axoff[l] = ((size_t)(b * 2048 + t)) * 1024;
    }

    PIPE_MAIN(g_Xh, g_Xl, axoff[l], g_Ph, g_Pl)

#pragma unroll
    for (int i = 0; i < 2; i++)
#pragma unroll
        for (int j = 0; j < 2; j++)
            wmma::store_matrix_sync(&Cs[wr * 32 + i * 16][wc * 32 + j * 16],
                                    acc[i][j], 68, wmma::mem_row_major);
    __syncthreads();
#pragma unroll
    for (int l = 0; l < 8; l++) {
        int id = tid + l * 128;
        int r = id >> 4, c4 = (id & 15) * 4;
        int rg = row0 + r;
        if (rg < NROW_U) {
            int b = rg / 2047, t = 1 + rg % 2047;
            float4 v = *(float4*)&Cs[r][c4];
            int col = col0 + c4;
            v.x += g_cvec[col + 0]; v.y += g_cvec[col + 1];
            v.z += g_cvec[col + 2]; v.w += g_cvec[col + 3];
            *(float4*)(out + ((size_t)(b * 2048 + t)) * 1024 + col) = v;
        }
    }
}

// --------------------------------------------------------------------------
// out[b,0,:] = x[b,0,:] ; V0 rows 0..7 = y_0 (fp32 + bf16 mirror buf 0)
__global__ void k_init(const float* __restrict__ x, float* __restrict__ out)
{
    int idx = blockIdx.x * blockDim.x + threadIdx.x;   // 8192
    int b = idx >> 10, e = idx & 1023;
    float v = x[((size_t)b * 2048) * 1024 + e];
    out[((size_t)b * 2048) * 1024 + e] = v;
    g_V0[idx] = v;
    bsplit(v, g_Vh[0][idx], g_Vl[0][idx]);
}

// --------------------------------------------------------------------------
// Pass 1 step s (pipelined): w <- Q @ w + u_{32k+s}, chunks 0..62.
__global__ void __launch_bounds__(128)
k_pass1(const float* __restrict__ u, int s)
{
    const int wb = s & 1, rbuf = wb ^ 1;
    const __nv_bfloat16* Wih = g_Wsh[rbuf];
    const __nv_bfloat16* Wil = g_Wsl[rbuf];
    __nv_bfloat16* Woh = g_Wsh[wb];
    __nv_bfloat16* Wol = g_Wsl[wb];

    __shared__ __align__(16) char sm[2 * PBUF];
    float (*Cs)[68] = (float(*)[68])sm;

    const int tid  = threadIdx.x;
    const int warp = tid >> 5;
    const int wr   = warp >> 1, wc = warp & 1;
    const int row0 = blockIdx.y * 64, col0 = blockIdx.x * 64;

    bfc_t acc[2][2];
#pragma unroll
    for (int i = 0; i < 2; i++)
#pragma unroll
        for (int j = 0; j < 2; j++) wmma::fill_fragment(acc[i][j], 0.f);

    if (s > 1) {
        size_t aroff[2];
#pragma unroll
        for (int l = 0; l < 2; l++) {
            int r = (tid + l * 128) >> 2;
            int rg = row0 + r;
            aroff[l] = (size_t)((rg < R1) ? rg : 0) * 1024;
        }
        PIPE_MAIN(Wih, Wil, aroff[l], g_Qh, g_Ql)
    }
#pragma unroll
    for (int i = 0; i < 2; i++)
#pragma unroll
        for (int j = 0; j < 2; j++)
            wmma::store_matrix_sync(&Cs[wr * 32 + i * 16][wc * 32 + j * 16],
                                    acc[i][j], 68, wmma::mem_row_major);
    __syncthreads();
#pragma unroll
    for (int l = 0; l < 8; l++) {
        int id = tid + l * 128;
        int r = id >> 4, c4 = (id & 15) * 4;
        int rg = row0 + r;
        if (rg < R1) {
            int ch = rg >> 3, b = rg & 7;
            int t = ch * SCH + s;
            int col = col0 + c4;
            float4 uv = *(const float4*)(u + ((size_t)(b * 2048 + t)) * 1024 + col);
            float4 av = *(float4*)&Cs[r][c4];
            av.x += uv.x; av.y += uv.y; av.z += uv.z; av.w += uv.w;
            size_t soff = (size_t)rg * 1024 + col;
            __nv_bfloat162 hh, ll;
            __nv_bfloat16 h, lo;
            bsplit(av.x, h, lo); hh.x = h; ll.x = lo;
            bsplit(av.y, h, lo); hh.y = h; ll.y = lo;
            *(__nv_bfloat162*)(Woh + soff)     = hh;
            *(__nv_bfloat162*)(Wol + soff)     = ll;
            bsplit(av.z, h, lo); hh.x = h; ll.x = lo;
            bsplit(av.w, h, lo); hh.y = h; ll.y = lo;
            *(__nv_bfloat162*)(Woh + soff + 2) = hh;
            *(__nv_bfloat162*)(Wol + soff + 2) = ll;
            if (s == SCH) {
                size_t voff = (size_t)(rg + 8) * 1024 + col;
                *(float4*)(g_V0 + voff) = av;
                bsplit(av.x, g_Vh[0][voff + 0], g_Vl[0][voff + 0]);
                bsplit(av.y, g_Vh[0][voff + 1], g_Vl[0][voff + 1]);
                bsplit(av.z, g_Vh[0][voff + 2], g_Vl[0][voff + 2]);
                bsplit(av.w, g_Vh[0][voff + 3], g_Vl[0][voff + 3]);
            }
        }
    }
}

// --------------------------------------------------------------------------
// Pass 2 step s (pipelined): y_{32k+s} = u + Q y_{32k+s-1}, in place in out.
__global__ void __launch_bounds__(128)
k_pass2(float* __restrict__ y, int s)
{
    const int rbuf = s & 1, wb = rbuf ^ 1;
    const __nv_bfloat16* Yih = g_Ysh[rbuf];
    const __nv_bfloat16* Yil = g_Ysl[rbuf];
    __nv_bfloat16* Yoh = g_Ysh[wb];
    __nv_bfloat16* Yol = g_Ysl[wb];

    __shared__ __align__(16) char sm[2 * PBUF];
    float (*Cs)[68] = (float(*)[68])sm;

    const int tid  = threadIdx.x;
    const int warp = tid >> 5;
    const int wr   = warp >> 1, wc = warp & 1;
    const int row0 = blockIdx.y * 64, col0 = blockIdx.x * 64;

    bfc_t acc[2][2];
#pragma unroll
    for (int i = 0; i < 2; i++)
#pragma unroll
        for (int j = 0; j < 2; j++) wmma::fill_fragment(acc[i][j], 0.f);

    {
        size_t aroff[2];
#pragma unroll
        for (int l = 0; l < 2; l++) {
            int r = (tid + l * 128) >> 2;
            aroff[l] = (size_t)(row0 + r) * 1024;
        }
        PIPE_MAIN(Yih, Yil, aroff[l], g_Qh, g_Ql)
    }
#pragma unroll
    for (int i = 0; i < 2; i++)
#pragma unroll
        for (int j = 0; j < 2; j++)
            wmma::store_matrix_sync(&Cs[wr * 32 + i * 16][wc * 32 + j * 16],
                                    acc[i][j], 68, wmma::mem_row_major);
    __syncthreads();
#pragma unroll
    for (int l = 0; l < 8; l++) {
        int id = tid + l * 128;
        int r = id >> 4, c4 = (id & 15) * 4;
        int rg = row0 + r;
        int ch = rg >> 3, b = rg & 7;
        int t = ch * SCH + s;
        if (t < LSEQ) {
            int col = col0 + c4;
            float* yp = y + ((size_t)(b * 2048 + t)) * 1024 + col;
            float4 yv = *(float4*)yp;
            float4 av = *(float4*)&Cs[r][c4];
            yv.x += av.x; yv.y += av.y; yv.z += av.z; yv.w += av.w;
            *(float4*)yp = yv;
            size_t soff = (size_t)rg * 1024 + col;
            __nv_bfloat162 hh, ll;
            __nv_bfloat16 h, lo;
            bsplit(yv.x, h, lo); hh.x = h; ll.x = lo;
            bsplit(yv.y, h, lo); hh.y = h; ll.y = lo;
            *(__nv_bfloat162*)(Yoh + soff)     = hh;
            *(__nv_bfloat162*)(Yol + soff)     = ll;
            bsplit(yv.z, h, lo); hh.x = h; ll.x = lo;
            bsplit(yv.w, h, lo); hh.y = h; ll.y = lo;
            *(__nv_bfloat162*)(Yoh + soff + 2) = hh;
            *(__nv_bfloat162*)(Yol + soff + 2) = ll;
        }
    }
}

// --------------------------------------------------------------------------
extern "C" void kernel_launch(void* const* d_in, const int* in_sizes, int n_in,
                              void* d_out, int out_size)
{
    const float* x    = (const float*)d_in[0];
    const float* A_w  = (const float*)d_in[1];
    const float* C_w  = (const float*)d_in[2];
    const float* rc_w = (const float*)d_in[3];
    const float* rc_b = (const float*)d_in[4];
    float* out = (float*)d_out;

    dim3 gsq(16, 16);       // 1024x1024: 16x16 tiles of 64x64
    dim3 gps(16, 8);        // pass/scan kernels: 16 col-tiles x 8 row-tiles

    k_prep_wy<<<4096, 256>>>(rc_w);
    k_split_x<<<65536, 256>>>(x);
    // M = C_w @ A_w
    k_nn<<<gsq, 128>>>(C_w, A_w, -1, -1, BUF_M, 1024);
    // P = M @ Wx (Wx = rc_w[:, :1024], ldb = 3072)
    k_nn<<<gsq, 128>>>(0, rc_w, BUF_M, -1, BUF_P, 3072);
    k_split<<<4096, 256>>>(0);
    // Q = M @ Wy
    k_nn<<<gsq, 128>>>(0, 0, BUF_M, BUF_WY, BUF_Q, 1024);
    k_split<<<4096, 256>>>(1);
    // c = M @ rc_b
    k_matvec_c<<<128, 256>>>(rc_b);
    // U into d_out (t = 1..2047)
    k_nt_u<<<dim3(16, 256), 128>>>(out);
    // Q^32 via 5 pipelined bf16 squarings
    k_pow<<<gsq, 128>>>(PW_Q,  PW_T1);    // Q^2
    k_pow<<<gsq, 128>>>(PW_T1, PW_T2);    // Q^4
    k_pow<<<gsq, 128>>>(PW_T2, PW_T1);    // Q^8
    k_pow<<<gsq, 128>>>(PW_T1, PW_T2);    // Q^16
    k_pow<<<gsq, 128>>>(PW_T2, PW_QS);    // Q^32
    // y_0 -> out and V0 rows 0..7
    k_init<<<32, 256>>>(x, out);
    // pass 1 (s==32 deposits chunk-end sums into V0 rows 8..511)
    for (int s = 1; s <= SCH; s++)
        k_pass1<<<gps, 128>>>(out, s);
    // Kogge-Stone carry scan: offsets 1,2,4,8,16,32 (powers of Q^32)
    k_scan<<<gps, 128>>>(0, PW_QS, 8);                        // o=1
    k_pow<<<gsq, 128>>>(PW_QS, PW_T1);                        // Q^64
    k_scan<<<gps, 128>>>(1, PW_T1, 16);                       // o=2
    k_pow<<<gsq, 128>>>(PW_T1, PW_T2);                        // Q^128
    k_scan<<<gps, 128>>>(0, PW_T2, 32);                       // o=4
    k_pow<<<gsq, 128>>>(PW_T2, PW_T1);                        // Q^256
    k_scan<<<gps, 128>>>(1, PW_T1, 64);                       // o=8
    k_pow<<<gsq, 128>>>(PW_T1, PW_T2);                        // Q^512
    k_scan<<<gps, 128>>>(0, PW_T2, 128);                      // o=16
    k_pow<<<gsq, 128>>>(PW_T2, PW_T1);                        // Q^1024
    k_scan<<<gps, 128>>>(1, PW_T1, 256);                      // o=32
    // seed pass-2 state from scanned carries (V0)
    k_seed<<<2048, 256>>>();
    // pass 2
    for (int s = 1; s <= SCH; s++)
        k_pass2<<<gps, 128>>>(out, s);
}